// round 1
// baseline (speedup 1.0000x reference)
#include <cuda_runtime.h>
#include <cuda_bf16.h>

// ContrastiveLoss: n=4096 rows (2 views x 32 classes x 64), F=128.
// Plan:
//   k_init : zero per-row accumulators, decode overlap_inds (dtype-sniffed),
//            build labels[4096] (uint8).
//   k_main : fused 4096x4096x128 fp32 GEMM + epilogue. Per row accumulates
//            fullsum(exp), samesum(exp over same-label incl diag),
//            S = sum_same w*logit, max over neg logits; scatters same-label
//            logits to g_pos[row][idx] for the accuracy pass.
//   k_rows : per row: negsum = full - same; loss += W*log(negsum) - (S - x_self);
//            correct += #pos logits > max_neg.
//   k_fin  : out[0]=acc, out[1]=loss.

#define NTOT 4096
#define NH   2048
#define FD   128
#define KCLS 32
#define TEMPC 0.01f
#define PADW 132

__device__ float        g_full[NTOT];
__device__ float        g_same[NTOT];
__device__ float        g_S[NTOT];
__device__ unsigned int g_maxenc[NTOT];
__device__ float        g_pos[NTOT][128];
__device__ unsigned char g_lab[NTOT];
__device__ unsigned char g_ov[KCLS];
__device__ float        g_loss;
__device__ int          g_corr;
__device__ int          g_np;

__device__ __forceinline__ unsigned int encf(float f) {
    unsigned int u = __float_as_uint(f);
    return (u & 0x80000000u) ? ~u : (u | 0x80000000u);
}
__device__ __forceinline__ float decf(unsigned int v) {
    unsigned int u = (v & 0x80000000u) ? (v & 0x7FFFFFFFu) : ~v;
    return __uint_as_float(u);
}

__global__ void k_init(const unsigned char* __restrict__ ovraw) {
    int tid = threadIdx.x;
    for (int i = tid; i < NTOT; i += blockDim.x) {
        g_full[i] = 0.f; g_same[i] = 0.f; g_S[i] = 0.f; g_maxenc[i] = 0u;
    }
    if (tid == 0) { g_loss = 0.f; g_corr = 0; g_np = 0; }

    __shared__ unsigned char cls2[KCLS];
    if (tid == 0) {
        // Sniff overlap_inds dtype: float32 (0.0/1.0), int32 (0/1), or byte bool.
        int mode;
        const unsigned int* u32p = (const unsigned int*)ovraw;
        bool allF = true, anyF = false;
        for (int c = 0; c < 8; c++) {
            unsigned int u = u32p[c];
            if (u != 0u && u != 0x3F800000u) allF = false;
            if (u == 0x3F800000u) anyF = true;
        }
        if (allF && anyF) mode = 2;               // float32
        else {
            bool oddNZ = false;
            for (int i = 0; i < 32; i++) if ((i & 3) && ovraw[i]) oddNZ = true;
            mode = oddNZ ? 0 : 1;                 // 0 = byte bool, 1 = int32
        }
        int run = 0;
        for (int c = 0; c < KCLS; c++) {
            bool ov;
            if (mode == 0)      ov = ovraw[c] != 0;
            else if (mode == 1) ov = ((const int*)ovraw)[c] != 0;
            else                ov = ((const float*)ovraw)[c] != 0.f;
            g_ov[c] = ov ? 1 : 0;
            cls2[c] = ov ? (unsigned char)c : (unsigned char)(KCLS + run);
            if (!ov) run++;
        }
    }
    __syncthreads();
    for (int i = tid; i < NH; i += blockDim.x) {
        g_lab[i]      = (unsigned char)(i >> 6);
        g_lab[NH + i] = cls2[i >> 6];
    }
}

__global__ void __launch_bounds__(256, 1)
k_main(const float* __restrict__ f1, const float* __restrict__ f2) {
    extern __shared__ float sm[];
    float* As = sm;                       // [k][m], padded row = 132 floats
    float* Bs = sm + 128 * PADW;          // [k][c]
    unsigned char* labc = (unsigned char*)(sm + 2 * 128 * PADW);

    const int tid = threadIdx.x;
    const int tx = tid & 15, ty = tid >> 4;
    const int rowbase = blockIdx.x * 128;
    const float* Asrc = (rowbase < NH) ? (f1 + (size_t)rowbase * FD)
                                       : (f2 + (size_t)(rowbase - NH) * FD);
    // Load A row-block transposed into smem (once per CTA).
    #pragma unroll
    for (int it = 0; it < 16; ++it) {
        int linear = (it * 256 + tid) * 4;
        int kk = linear & 127, m = linear >> 7;
        float4 v = *(const float4*)(Asrc + m * FD + kk);
        As[(kk + 0) * PADW + m] = v.x;
        As[(kk + 1) * PADW + m] = v.y;
        As[(kk + 2) * PADW + m] = v.z;
        As[(kk + 3) * PADW + m] = v.w;
    }
    const int r0 = rowbase + ty * 8;
    unsigned char labi[8];
    #pragma unroll
    for (int p = 0; p < 8; p++) labi[p] = g_lab[r0 + p];
    const bool is2i = rowbase >= NH;

    float full[8], sme[8], Sa[8], mx[8];
    #pragma unroll
    for (int p = 0; p < 8; p++) { full[p] = 0.f; sme[p] = 0.f; Sa[p] = 0.f; mx[p] = -1e30f; }

    #pragma unroll 1
    for (int t = 0; t < 8; ++t) {
        const int colbase = blockIdx.y * 1024 + t * 128;
        const float* Bsrc = (colbase < NH) ? (f1 + (size_t)colbase * FD)
                                           : (f2 + (size_t)(colbase - NH) * FD);
        __syncthreads();   // previous tile fully consumed before overwrite
        #pragma unroll
        for (int it = 0; it < 16; ++it) {
            int linear = (it * 256 + tid) * 4;
            int kk = linear & 127, c = linear >> 7;
            float4 v = *(const float4*)(Bsrc + c * FD + kk);
            Bs[(kk + 0) * PADW + c] = v.x;
            Bs[(kk + 1) * PADW + c] = v.y;
            Bs[(kk + 2) * PADW + c] = v.z;
            Bs[(kk + 3) * PADW + c] = v.w;
        }
        if (tid < 128) labc[tid] = g_lab[colbase + tid];
        __syncthreads();

        float acc[8][8];
        #pragma unroll
        for (int p = 0; p < 8; p++)
            #pragma unroll
            for (int q = 0; q < 8; q++) acc[p][q] = 0.f;

        #pragma unroll 4
        for (int kk = 0; kk < 128; ++kk) {
            float a[8], b[8];
            *(float4*)&a[0] = *(const float4*)&As[kk * PADW + ty * 8];
            *(float4*)&a[4] = *(const float4*)&As[kk * PADW + ty * 8 + 4];
            *(float4*)&b[0] = *(const float4*)&Bs[kk * PADW + tx * 8];
            *(float4*)&b[4] = *(const float4*)&Bs[kk * PADW + tx * 8 + 4];
            #pragma unroll
            for (int p = 0; p < 8; p++)
                #pragma unroll
                for (int q = 0; q < 8; q++)
                    acc[p][q] = fmaf(a[p], b[q], acc[p][q]);
        }

        // Epilogue: exp via FMA-pipe 2^f polynomial (keep MUFU idle).
        const bool is2j = colbase >= NH;
        const float w = (is2i != is2j) ? 0.5f : 1.0f;
        #pragma unroll
        for (int q = 0; q < 8; q++) {
            unsigned char lq = labc[tx * 8 + q];
            int j = colbase + tx * 8 + q;
            #pragma unroll
            for (int p = 0; p < 8; p++) {
                float x = acc[p][q] * TEMPC;
                float y = x * 1.44269504f;
                float tt = y + 12582912.f;            // round-to-nearest int
                float fr = y - (tt - 12582912.f);
                int ki = __float_as_int(tt) - 0x4B400000;
                float pl = 0.00133336f;
                pl = fmaf(pl, fr, 0.00961813f);
                pl = fmaf(pl, fr, 0.05550411f);
                pl = fmaf(pl, fr, 0.24022651f);
                pl = fmaf(pl, fr, 0.69314718f);
                pl = fmaf(pl, fr, 1.0f);
                float e = pl * __int_as_float((ki + 127) << 23);
                full[p] += e;
                if (lq == labi[p]) {
                    sme[p] += e;
                    Sa[p] = fmaf(w, x, Sa[p]);
                    int idx = (j & 63) + ((is2j && labi[p] < KCLS) ? 64 : 0);
                    g_pos[r0 + p][idx] = x;
                } else {
                    mx[p] = fmaxf(mx[p], x);
                }
            }
        }
    }

    // Reduce across the 16 tx-lanes sharing each row (xor stays in half-warp).
    #pragma unroll
    for (int p = 0; p < 8; p++) {
        float f = full[p], s = sme[p], ss = Sa[p], m = mx[p];
        #pragma unroll
        for (int o = 1; o < 16; o <<= 1) {
            f  += __shfl_xor_sync(0xffffffffu, f,  o);
            s  += __shfl_xor_sync(0xffffffffu, s,  o);
            ss += __shfl_xor_sync(0xffffffffu, ss, o);
            m = fmaxf(m, __shfl_xor_sync(0xffffffffu, m, o));
        }
        if (tx == 0) {
            atomicAdd(&g_full[r0 + p], f);
            atomicAdd(&g_same[r0 + p], s);
            atomicAdd(&g_S[r0 + p], ss);
            atomicMax(&g_maxenc[r0 + p], encf(m));
        }
    }
}

__global__ void k_rows() {
    int row = blockIdx.x * blockDim.x + threadIdx.x;
    float lossv = 0.f; int corr = 0, np = 0;
    if (row < NTOT) {
        int L = g_lab[row];
        bool ovl = (L < KCLS) ? (g_ov[L] != 0) : false;
        int cnt = ovl ? 128 : 64;
        int selfidx = (row & 63) + ((row >= NH && L < KCLS) ? 64 : 0);
        float xself = g_pos[row][selfidx];
        float negsum = g_full[row] - g_same[row];
        float S = g_S[row] - xself;
        float W = ovl ? 95.0f : 63.0f;
        np = cnt - 1;
        float mn = decf(g_maxenc[row]);
        for (int t2 = 0; t2 < cnt; t2++) {
            if (t2 != selfidx && g_pos[row][t2] > mn) corr++;
        }
        lossv = fmaf(W, logf(negsum), -S);
    }
    atomicAdd(&g_loss, lossv);
    atomicAdd(&g_corr, corr);
    atomicAdd(&g_np, np);
}

__global__ void k_fin(float* out, int out_size) {
    float np = (float)g_np;
    if (out_size >= 1) out[0] = (float)g_corr / np;
    if (out_size >= 2) out[1] = g_loss / np;
}

extern "C" void kernel_launch(void* const* d_in, const int* in_sizes, int n_in,
                              void* d_out, int out_size) {
    const float* f1 = nullptr;
    const float* f2 = nullptr;
    const unsigned char* ov = nullptr;
    for (int i = 0; i < n_in; i++) {
        if (in_sizes[i] == NH * FD) {
            if (!f1) f1 = (const float*)d_in[i];
            else if (!f2) f2 = (const float*)d_in[i];
        } else if (in_sizes[i] == KCLS) {
            ov = (const unsigned char*)d_in[i];
        }
    }
    size_t smem = (size_t)(2 * 128 * PADW) * sizeof(float) + 128;
    cudaFuncSetAttribute(k_main, cudaFuncAttributeMaxDynamicSharedMemorySize, (int)smem);

    k_init<<<1, 256>>>(ov);
    dim3 g1(32, 4);
    k_main<<<g1, 256, smem>>>(f1, f2);
    k_rows<<<32, 128>>>();
    k_fin<<<1, 1>>>((float*)d_out, out_size);
}

// round 3
// speedup vs baseline: 3.0299x; 3.0299x over previous
#include <cuda_runtime.h>
#include <cuda_bf16.h>

// ContrastiveLoss on GB300 — mma.sync (HMMA) bf16-split GEMM.
// tcgen05 is unavailable: the harness builds via plain compute_103 PTX, which
// rejects all tcgen05/.cta_group instructions. mma.sync bf16 has no arch gate.
//
//   k_init : zero accumulators, decode overlap_inds, build labels.
//   k_main : 32x32 grid of 128x128 tiles. fp32 -> bf16 hi/lo split in SMEM
//            (256B rows, xor-swizzled for ldmatrix), 3-pass m16n8k16 bf16 MMA
//            (hi*hi + hi*lo + lo*hi) -> exact-ish fp32 logits. Epilogue: exp
//            poly, per-row full/same/S/max via quad-shfl + smem atomics ->
//            global atomics; scatter same-label logits to g_pos.
//   k_rows : per-row loss + accuracy count; last block writes out[].

#define NTOT 4096
#define NH   2048
#define FD   128
#define KCLS 32
#define TEMPC 0.01f

__device__ float         g_full[NTOT];
__device__ float         g_same[NTOT];
__device__ float         g_S[NTOT];
__device__ unsigned int  g_maxenc[NTOT];
__device__ float         g_pos[NTOT][128];
__device__ unsigned char g_lab[NTOT];
__device__ unsigned char g_ov[KCLS];
__device__ float         g_loss;
__device__ int           g_corr;
__device__ int           g_np;
__device__ unsigned int  g_done;

__device__ __forceinline__ unsigned int encf(float f) {
    unsigned int u = __float_as_uint(f);
    return (u & 0x80000000u) ? ~u : (u | 0x80000000u);
}
__device__ __forceinline__ float decf(unsigned int v) {
    unsigned int u = (v & 0x80000000u) ? (v & 0x7FFFFFFFu) : ~v;
    return __uint_as_float(u);
}

__global__ void k_init(const unsigned char* __restrict__ ovraw) {
    int tid = threadIdx.x;
    for (int i = tid; i < NTOT; i += blockDim.x) {
        g_full[i] = 0.f; g_same[i] = 0.f; g_S[i] = 0.f; g_maxenc[i] = 0u;
    }
    if (tid == 0) { g_loss = 0.f; g_corr = 0; g_np = 0; g_done = 0u; }

    __shared__ unsigned char cls2[KCLS];
    if (tid == 0) {
        int mode;
        const unsigned int* u32p = (const unsigned int*)ovraw;
        bool allF = true, anyF = false;
        for (int c = 0; c < 8; c++) {
            unsigned int u = u32p[c];
            if (u != 0u && u != 0x3F800000u) allF = false;
            if (u == 0x3F800000u) anyF = true;
        }
        if (allF && anyF) mode = 2;
        else {
            bool oddNZ = false;
            for (int i = 0; i < 32; i++) if ((i & 3) && ovraw[i]) oddNZ = true;
            mode = oddNZ ? 0 : 1;
        }
        int run = 0;
        for (int c = 0; c < KCLS; c++) {
            bool ov;
            if (mode == 0)      ov = ovraw[c] != 0;
            else if (mode == 1) ov = ((const int*)ovraw)[c] != 0;
            else                ov = ((const float*)ovraw)[c] != 0.f;
            g_ov[c] = ov ? 1 : 0;
            cls2[c] = ov ? (unsigned char)c : (unsigned char)(KCLS + run);
            if (!ov) run++;
        }
    }
    __syncthreads();
    for (int i = tid; i < NH; i += blockDim.x) {
        g_lab[i]      = (unsigned char)(i >> 6);
        g_lab[NH + i] = cls2[i >> 6];
    }
}

// ---------------- helpers ----------------

__device__ __forceinline__ unsigned smem_u32(const void* p) {
    unsigned a;
    asm("{ .reg .u64 t; cvta.to.shared.u64 t, %1; cvt.u32.u64 %0, t; }"
        : "=r"(a) : "l"(p));
    return a;
}

#define LDSM4(r, a) \
    asm volatile("ldmatrix.sync.aligned.m8n8.x4.shared.b16 {%0,%1,%2,%3}, [%4];" \
        : "=r"((r)[0]), "=r"((r)[1]), "=r"((r)[2]), "=r"((r)[3]) : "r"(a))

#define MMA(c, a, b0, b1) \
    asm volatile("mma.sync.aligned.m16n8k16.row.col.f32.bf16.bf16.f32 " \
        "{%0,%1,%2,%3}, {%4,%5,%6,%7}, {%8,%9}, {%0,%1,%2,%3};" \
        : "+f"((c)[0]), "+f"((c)[1]), "+f"((c)[2]), "+f"((c)[3]) \
        : "r"((a)[0]), "r"((a)[1]), "r"((a)[2]), "r"((a)[3]), "r"(b0), "r"(b1))

__device__ __forceinline__ unsigned pack2(float a, float b) {
    __nv_bfloat162 t = __floats2bfloat162_rn(a, b);
    return *(unsigned*)&t;
}

// 128x128 bf16 tile: 256B rows, 16B chunks xor-swizzled by (row&7).
__device__ __forceinline__ void store_split(char* sm, int hi_off, int lo_off,
                                            int row, int kq, float4 v) {
    __nv_bfloat16 h0 = __float2bfloat16(v.x);
    __nv_bfloat16 h1 = __float2bfloat16(v.y);
    __nv_bfloat16 h2 = __float2bfloat16(v.z);
    __nv_bfloat16 h3 = __float2bfloat16(v.w);
    float l0 = v.x - __bfloat162float(h0);
    float l1 = v.y - __bfloat162float(h1);
    float l2 = v.z - __bfloat162float(h2);
    float l3 = v.w - __bfloat162float(h3);
    unsigned so = (unsigned)row * 256u
                + ((((unsigned)(kq >> 3)) ^ ((unsigned)row & 7u)) << 4)
                + (((unsigned)kq & 7u) << 1);
    unsigned hp0, hp1;
    {
        __nv_bfloat162 t01; t01.x = h0; t01.y = h1; hp0 = *(unsigned*)&t01;
        __nv_bfloat162 t23; t23.x = h2; t23.y = h3; hp1 = *(unsigned*)&t23;
    }
    *(uint2*)(sm + hi_off + so) = make_uint2(hp0, hp1);
    *(uint2*)(sm + lo_off + so) = make_uint2(pack2(l0, l1), pack2(l2, l3));
}

// ---------------- main kernel ----------------

#define SM_AHI  0
#define SM_ALO  32768
#define SM_BHI  65536
#define SM_BLO  98304
#define SM_LABC 131072
#define SM_LABR 131200
#define SM_RED  131328               // s_full[128], s_same[128], s_S[128], s_mx[128]
#define SM_TOTAL (131328 + 4 * 512)

__global__ void __launch_bounds__(256, 1)
k_main(const float* __restrict__ f1, const float* __restrict__ f2) {
    extern __shared__ char smc[];
    unsigned sbase = smem_u32(smc);
    float* s_full = (float*)(smc + SM_RED);
    float* s_same = s_full + 128;
    float* s_S    = s_same + 128;
    unsigned* s_mx = (unsigned*)(s_S + 128);

    const int tid = threadIdx.x, wid = tid >> 5, lane = tid & 31;
    const int rowbase = blockIdx.y << 7, colbase = blockIdx.x << 7;
    const int m0 = (wid >> 2) << 6;      // 0 or 64
    const int n0 = (wid & 3) << 5;       // 0,32,64,96

    if (tid < 128) {
        smc[SM_LABC + tid] = (char)g_lab[colbase + tid];
        smc[SM_LABR + tid] = (char)g_lab[rowbase + tid];
        s_full[tid] = 0.f; s_same[tid] = 0.f; s_S[tid] = 0.f; s_mx[tid] = 0u;
    }

    const float* Asrc = (rowbase < NH) ? f1 + (size_t)rowbase * FD
                                       : f2 + (size_t)(rowbase - NH) * FD;
    const float* Bsrc = (colbase < NH) ? f1 + (size_t)colbase * FD
                                       : f2 + (size_t)(colbase - NH) * FD;

    #pragma unroll
    for (int it = 0; it < 16; ++it) {
        int idx = it * 256 + tid;                 // 0..4095 float4 slots
        int row = idx >> 5, kq = (idx & 31) << 2;
        float4 va = *(const float4*)(Asrc + row * FD + kq);
        store_split(smc, SM_AHI, SM_ALO, row, kq, va);
        float4 vb = *(const float4*)(Bsrc + row * FD + kq);
        store_split(smc, SM_BHI, SM_BLO, row, kq, vb);
    }
    __syncthreads();

    // ldmatrix lane geometry
    const int rA  = ((lane >> 3) & 1) * 8 + (lane & 7);   // A row-in-16
    const int kbA = (lane >> 4) & 1;                      // A k-half
    const int rB  = ((lane >> 4) & 1) * 8 + (lane & 7);   // B n-in-16
    const int kbB = (lane >> 3) & 1;                      // B k-half

    float acc[4][4][4];
    #pragma unroll
    for (int mi = 0; mi < 4; mi++)
        #pragma unroll
        for (int ni = 0; ni < 4; ni++)
            #pragma unroll
            for (int u = 0; u < 4; u++) acc[mi][ni][u] = 0.f;

    #pragma unroll 2
    for (int ks = 0; ks < 8; ++ks) {
        unsigned aHi[4][4], aLo[4][4], bHi[2][4], bLo[2][4];
        #pragma unroll
        for (int mi = 0; mi < 4; mi++) {
            unsigned ro = (unsigned)(m0 + mi * 16 + rA) * 256u;
            unsigned ch = ((unsigned)((ks * 2 + kbA) ^ (rA & 7))) << 4;
            LDSM4(aHi[mi], sbase + SM_AHI + ro + ch);
            LDSM4(aLo[mi], sbase + SM_ALO + ro + ch);
        }
        #pragma unroll
        for (int nj = 0; nj < 2; nj++) {
            unsigned ro = (unsigned)(n0 + nj * 16 + rB) * 256u;
            unsigned ch = ((unsigned)((ks * 2 + kbB) ^ (rB & 7))) << 4;
            LDSM4(bHi[nj], sbase + SM_BHI + ro + ch);
            LDSM4(bLo[nj], sbase + SM_BLO + ro + ch);
        }
        #pragma unroll
        for (int mi = 0; mi < 4; mi++)
            #pragma unroll
            for (int ni = 0; ni < 4; ni++) {
                int p = ni >> 1, s = (ni & 1) * 2;
                MMA(acc[mi][ni], aHi[mi], bHi[p][s], bHi[p][s + 1]);
                MMA(acc[mi][ni], aHi[mi], bLo[p][s], bLo[p][s + 1]);
                MMA(acc[mi][ni], aLo[mi], bHi[p][s], bHi[p][s + 1]);
            }
    }

    // ---------------- epilogue ----------------
    const bool is2i = rowbase >= NH, is2j = colbase >= NH;
    const float wgt = (is2i != is2j) ? 0.5f : 1.0f;
    const int grp = lane >> 2, t4 = lane & 3;

    #pragma unroll
    for (int mi = 0; mi < 4; mi++) {
        #pragma unroll
        for (int h = 0; h < 2; h++) {
            int rloc = m0 + mi * 16 + grp + h * 8;
            int grow = rowbase + rloc;
            unsigned char labi = (unsigned char)smc[SM_LABR + rloc];
            float full = 0.f, sme = 0.f, Sa = 0.f, mx = -1e30f;
            #pragma unroll
            for (int ni = 0; ni < 4; ni++) {
                #pragma unroll
                for (int u = 0; u < 2; u++) {
                    float x = acc[mi][ni][h * 2 + u] * TEMPC;
                    float y = x * 1.44269504f;
                    float tt = y + 12582912.f;
                    float fr = y - (tt - 12582912.f);
                    int ki = __float_as_int(tt) - 0x4B400000;
                    float pl = 0.00133336f;
                    pl = fmaf(pl, fr, 0.00961813f);
                    pl = fmaf(pl, fr, 0.05550411f);
                    pl = fmaf(pl, fr, 0.24022651f);
                    pl = fmaf(pl, fr, 0.69314718f);
                    pl = fmaf(pl, fr, 1.0f);
                    float e = pl * __int_as_float((ki + 127) << 23);
                    full += e;
                    int cloc = n0 + ni * 8 + t4 * 2 + u;
                    unsigned char lq = (unsigned char)smc[SM_LABC + cloc];
                    if (lq == labi) {
                        sme += e;
                        Sa = fmaf(wgt, x, Sa);
                        int j = colbase + cloc;
                        int pidx = (j & 63) + ((is2j && labi < KCLS) ? 64 : 0);
                        g_pos[grow][pidx] = x;
                    } else {
                        mx = fmaxf(mx, x);
                    }
                }
            }
            // reduce across the 4 lanes of the quad (same row)
            #pragma unroll
            for (int o = 1; o < 4; o <<= 1) {
                full += __shfl_xor_sync(0xffffffffu, full, o);
                sme  += __shfl_xor_sync(0xffffffffu, sme,  o);
                Sa   += __shfl_xor_sync(0xffffffffu, Sa,   o);
                mx = fmaxf(mx, __shfl_xor_sync(0xffffffffu, mx, o));
            }
            if (t4 == 0) {
                atomicAdd(&s_full[rloc], full);
                atomicAdd(&s_same[rloc], sme);
                atomicAdd(&s_S[rloc], Sa);
                atomicMax(&s_mx[rloc], encf(mx));
            }
        }
    }
    __syncthreads();
    if (tid < 128) {
        int grow = rowbase + tid;
        atomicAdd(&g_full[grow], s_full[tid]);
        atomicAdd(&g_same[grow], s_same[tid]);
        atomicAdd(&g_S[grow], s_S[tid]);
        atomicMax(&g_maxenc[grow], s_mx[tid]);
    }
}

__global__ void k_rows(float* out, int out_size) {
    int row = blockIdx.x * blockDim.x + threadIdx.x;
    float lossv = 0.f; int corr = 0, np = 0;
    if (row < NTOT) {
        int L = g_lab[row];
        bool ovl = (L < KCLS) ? (g_ov[L] != 0) : false;
        int cnt = ovl ? 128 : 64;
        int selfidx = (row & 63) + ((row >= NH && L < KCLS) ? 64 : 0);
        float xself = g_pos[row][selfidx];
        float negsum = g_full[row] - g_same[row];
        float S = g_S[row] - xself;
        float W = ovl ? 95.0f : 63.0f;
        np = cnt - 1;
        float mn = decf(g_maxenc[row]);
        for (int t2 = 0; t2 < cnt; t2++) {
            if (t2 != selfidx && g_pos[row][t2] > mn) corr++;
        }
        lossv = fmaf(W, logf(negsum), -S);
    }
    atomicAdd(&g_loss, lossv);
    atomicAdd(&g_corr, corr);
    atomicAdd(&g_np, np);
    __syncthreads();
    if (threadIdx.x == 0) {
        __threadfence();
        unsigned done = atomicAdd(&g_done, 1u);
        if (done == gridDim.x - 1) {
            float npf = (float)g_np;
            if (out_size >= 1) out[0] = (float)g_corr / npf;
            if (out_size >= 2) out[1] = g_loss / npf;
        }
    }
}

extern "C" void kernel_launch(void* const* d_in, const int* in_sizes, int n_in,
                              void* d_out, int out_size) {
    const float* f1 = nullptr;
    const float* f2 = nullptr;
    const unsigned char* ov = nullptr;
    for (int i = 0; i < n_in; i++) {
        if (in_sizes[i] == NH * FD) {
            if (!f1) f1 = (const float*)d_in[i];
            else if (!f2) f2 = (const float*)d_in[i];
        } else if (in_sizes[i] == KCLS) {
            ov = (const unsigned char*)d_in[i];
        }
    }
    cudaFuncSetAttribute(k_main, cudaFuncAttributeMaxDynamicSharedMemorySize, SM_TOTAL);

    k_init<<<1, 256>>>(ov);
    k_main<<<dim3(32, 32), 256, SM_TOTAL>>>(f1, f2);
    k_rows<<<32, 128>>>((float*)d_out, out_size);
}

// round 5
// speedup vs baseline: 3.3471x; 1.1047x over previous
#include <cuda_runtime.h>
#include <cuda_bf16.h>

// ContrastiveLoss on GB300 — 3-pass bf16-split mma.sync GEMM, 2 launches,
// 2 CTAs/SM via B-tile staging.
//   k_main : 32x32 grid of 128x128 tiles, 256 thr. SMEM holds A_hi, A_lo and
//            ONE B tile (96KB -> occupancy 2). Passes: Ahi*Bhi, Alo*Bhi,
//            then reload B from L2 as lo and run Ahi*Blo. Exact-ish fp32
//            logits (residual ~ lo*lo ~ 1e-7 rel). Epilogue: exp poly,
//            per-row full/same/S/max into atomic-free partial arrays
//            [colblock][row]; scatter same-label logits to g_pos.
//   k_rows : reduce 32 partials/row, loss + accuracy, done-counter writes out.

#define NTOT 4096
#define NH   2048
#define FD   128
#define KCLS 32
#define TEMPC 0.01f

__device__ float         g_fullp[32][NTOT];
__device__ float         g_samep[32][NTOT];
__device__ float         g_Sp[32][NTOT];
__device__ unsigned int  g_mxp[32][NTOT];
__device__ float         g_pos[NTOT][128];
__device__ float         g_loss;
__device__ int           g_corr;
__device__ int           g_np;
__device__ unsigned int  g_done;

__device__ __forceinline__ unsigned int encf(float f) {
    unsigned int u = __float_as_uint(f);
    return (u & 0x80000000u) ? ~u : (u | 0x80000000u);
}
__device__ __forceinline__ float decf(unsigned int v) {
    unsigned int u = (v & 0x80000000u) ? (v & 0x7FFFFFFFu) : ~v;
    return __uint_as_float(u);
}

__device__ unsigned sniff_ov(const unsigned char* __restrict__ ovraw) {
    const unsigned* u32p = (const unsigned*)ovraw;
    bool allF = true, anyF = false;
    #pragma unroll
    for (int c = 0; c < 8; c++) {
        unsigned u = u32p[c];
        if (u != 0u && u != 0x3F800000u) allF = false;
        if (u == 0x3F800000u) anyF = true;
    }
    int mode;
    if (allF && anyF) mode = 2;
    else {
        bool oddNZ = false;
        for (int i = 0; i < 32; i++) if ((i & 3) && ovraw[i]) oddNZ = true;
        mode = oddNZ ? 0 : 1;
    }
    unsigned m = 0;
    for (int c = 0; c < 32; c++) {
        bool ov;
        if (mode == 0)      ov = ovraw[c] != 0;
        else if (mode == 1) ov = ((const int*)ovraw)[c] != 0;
        else                ov = ((const float*)ovraw)[c] != 0.f;
        m |= (ov ? 1u : 0u) << c;
    }
    return m;
}

__device__ __forceinline__ int labelOf(int i, unsigned ovm) {
    if (i < NH) return i >> 6;
    int c = (i - NH) >> 6;
    if ((ovm >> c) & 1u) return c;
    return KCLS + __popc((~ovm) & ((1u << c) - 1u));
}

// ---------------- helpers ----------------

__device__ __forceinline__ unsigned smem_u32(const void* p) {
    unsigned a;
    asm("{ .reg .u64 t; cvta.to.shared.u64 t, %1; cvt.u32.u64 %0, t; }"
        : "=r"(a) : "l"(p));
    return a;
}

#define LDSM4(r, a) \
    asm volatile("ldmatrix.sync.aligned.m8n8.x4.shared.b16 {%0,%1,%2,%3}, [%4];" \
        : "=r"((r)[0]), "=r"((r)[1]), "=r"((r)[2]), "=r"((r)[3]) : "r"(a))

#define MMA(c, a, b0, b1) \
    asm volatile("mma.sync.aligned.m16n8k16.row.col.f32.bf16.bf16.f32 " \
        "{%0,%1,%2,%3}, {%4,%5,%6,%7}, {%8,%9}, {%0,%1,%2,%3};" \
        : "+f"((c)[0]), "+f"((c)[1]), "+f"((c)[2]), "+f"((c)[3]) \
        : "r"((a)[0]), "r"((a)[1]), "r"((a)[2]), "r"((a)[3]), "r"(b0), "r"(b1))

__device__ __forceinline__ unsigned pack2(float a, float b) {
    __nv_bfloat162 t = __floats2bfloat162_rn(a, b);
    return *(unsigned*)&t;
}

__device__ __forceinline__ unsigned swz(int row, int kq) {
    return (unsigned)row * 256u
         + ((((unsigned)(kq >> 3)) ^ ((unsigned)row & 7u)) << 4)
         + (((unsigned)kq & 7u) << 1);
}

__device__ __forceinline__ void cvt_hilo(float4 v, uint2& hi, uint2& lo) {
    __nv_bfloat16 h0 = __float2bfloat16(v.x);
    __nv_bfloat16 h1 = __float2bfloat16(v.y);
    __nv_bfloat16 h2 = __float2bfloat16(v.z);
    __nv_bfloat16 h3 = __float2bfloat16(v.w);
    __nv_bfloat162 t01; t01.x = h0; t01.y = h1;
    __nv_bfloat162 t23; t23.x = h2; t23.y = h3;
    hi = make_uint2(*(unsigned*)&t01, *(unsigned*)&t23);
    lo = make_uint2(pack2(v.x - __bfloat162float(h0), v.y - __bfloat162float(h1)),
                    pack2(v.z - __bfloat162float(h2), v.w - __bfloat162float(h3)));
}

// ---------------- main kernel ----------------

#define SM_AHI  0
#define SM_ALO  32768
#define SM_B    65536
#define SM_LABC 98304
#define SM_LABR 98432
#define SM_RED  98560
#define SM_TOTAL (98560 + 4 * 512)

__global__ void __launch_bounds__(256, 2)
k_main(const float* __restrict__ f1, const float* __restrict__ f2,
       const unsigned char* __restrict__ ovraw) {
    extern __shared__ char smc[];
    unsigned sbase = smem_u32(smc);
    float* s_full = (float*)(smc + SM_RED);
    float* s_same = s_full + 128;
    float* s_S    = s_same + 128;
    unsigned* s_mx = (unsigned*)(s_S + 128);
    __shared__ unsigned s_ovm;

    const int tid = threadIdx.x, wid = tid >> 5, lane = tid & 31;
    const int rowbase = blockIdx.y << 7, colbase = blockIdx.x << 7;
    const int m0 = (wid >> 2) << 6;      // 0 or 64
    const int n0 = (wid & 3) << 5;       // 0,32,64,96

    if (tid == 0) {
        s_ovm = sniff_ov(ovraw);
        if (blockIdx.x == 0 && blockIdx.y == 0) {
            g_loss = 0.f; g_corr = 0; g_np = 0; g_done = 0u;
        }
    }
    __syncthreads();
    const unsigned ovm = s_ovm;

    if (tid < 128) {
        smc[SM_LABC + tid] = (char)labelOf(colbase + tid, ovm);
        smc[SM_LABR + tid] = (char)labelOf(rowbase + tid, ovm);
        s_full[tid] = 0.f; s_same[tid] = 0.f; s_S[tid] = 0.f; s_mx[tid] = 0u;
    }

    const float* Asrc = (rowbase < NH) ? f1 + (size_t)rowbase * FD
                                       : f2 + (size_t)(rowbase - NH) * FD;
    const float* Bsrc = (colbase < NH) ? f1 + (size_t)colbase * FD
                                       : f2 + (size_t)(colbase - NH) * FD;

    // Load A (hi+lo) and B (hi) into SMEM.
    #pragma unroll
    for (int it = 0; it < 16; ++it) {
        int idx = it * 256 + tid;                 // 4096 float4 slots
        int row = idx >> 5, kq = (idx & 31) << 2;
        unsigned so = swz(row, kq);
        uint2 hi, lo;
        cvt_hilo(*(const float4*)(Asrc + row * FD + kq), hi, lo);
        *(uint2*)(smc + SM_AHI + so) = hi;
        *(uint2*)(smc + SM_ALO + so) = lo;
        float4 vb = *(const float4*)(Bsrc + row * FD + kq);
        __nv_bfloat162 b01 = __floats2bfloat162_rn(vb.x, vb.y);
        __nv_bfloat162 b23 = __floats2bfloat162_rn(vb.z, vb.w);
        *(uint2*)(smc + SM_B + so) = make_uint2(*(unsigned*)&b01, *(unsigned*)&b23);
    }
    __syncthreads();

    const int rA  = ((lane >> 3) & 1) * 8 + (lane & 7);
    const int kbA = (lane >> 4) & 1;
    const int rB  = ((lane >> 4) & 1) * 8 + (lane & 7);
    const int kbB = (lane >> 3) & 1;
    const unsigned roA = (unsigned)(m0 + rA) * 256u;
    const unsigned roB = (unsigned)(n0 + rB) * 256u;

    float acc[4][4][4];
    #pragma unroll
    for (int mi = 0; mi < 4; mi++)
        #pragma unroll
        for (int ni = 0; ni < 4; ni++)
            #pragma unroll
            for (int u = 0; u < 4; u++) acc[mi][ni][u] = 0.f;

    // Pass 1: Ahi * Bhi ; Pass 2: Alo * Bhi
    #pragma unroll 1
    for (int pass = 0; pass < 2; ++pass) {
        const unsigned abase = (pass == 0) ? (sbase + SM_AHI) : (sbase + SM_ALO);
        #pragma unroll 4
        for (int ks = 0; ks < 8; ++ks) {
            unsigned aF[4][4], bF[2][4];
            unsigned chA = ((unsigned)((ks * 2 + kbA) ^ (rA & 7))) << 4;
            unsigned chB = ((unsigned)((ks * 2 + kbB) ^ (rB & 7))) << 4;
            #pragma unroll
            for (int mi = 0; mi < 4; mi++)
                LDSM4(aF[mi], abase + roA + (unsigned)(mi * 16) * 256u + chA);
            #pragma unroll
            for (int nj = 0; nj < 2; nj++)
                LDSM4(bF[nj], sbase + SM_B + roB + (unsigned)(nj * 16) * 256u + chB);
            #pragma unroll
            for (int mi = 0; mi < 4; mi++)
                #pragma unroll
                for (int ni = 0; ni < 4; ni++) {
                    int p = ni >> 1, s = (ni & 1) * 2;
                    MMA(acc[mi][ni], aF[mi], bF[p][s], bF[p][s + 1]);
                }
        }
    }

    // Swap B tile to lo (reload from L2).
    __syncthreads();
    #pragma unroll
    for (int it = 0; it < 16; ++it) {
        int idx = it * 256 + tid;
        int row = idx >> 5, kq = (idx & 31) << 2;
        uint2 hi, lo;
        cvt_hilo(*(const float4*)(Bsrc + row * FD + kq), hi, lo);
        *(uint2*)(smc + SM_B + swz(row, kq)) = lo;
    }
    __syncthreads();

    // Pass 3: Ahi * Blo
    #pragma unroll 4
    for (int ks = 0; ks < 8; ++ks) {
        unsigned aF[4][4], bF[2][4];
        unsigned chA = ((unsigned)((ks * 2 + kbA) ^ (rA & 7))) << 4;
        unsigned chB = ((unsigned)((ks * 2 + kbB) ^ (rB & 7))) << 4;
        #pragma unroll
        for (int mi = 0; mi < 4; mi++)
            LDSM4(aF[mi], sbase + SM_AHI + roA + (unsigned)(mi * 16) * 256u + chA);
        #pragma unroll
        for (int nj = 0; nj < 2; nj++)
            LDSM4(bF[nj], sbase + SM_B + roB + (unsigned)(nj * 16) * 256u + chB);
        #pragma unroll
        for (int mi = 0; mi < 4; mi++)
            #pragma unroll
            for (int ni = 0; ni < 4; ni++) {
                int p = ni >> 1, s = (ni & 1) * 2;
                MMA(acc[mi][ni], aF[mi], bF[p][s], bF[p][s + 1]);
            }
    }

    // ---------------- epilogue ----------------
    const bool is2i = rowbase >= NH, is2j = colbase >= NH;
    const float wgt = (is2i != is2j) ? 0.5f : 1.0f;
    const int grp = lane >> 2, t4 = lane & 3;

    #pragma unroll
    for (int mi = 0; mi < 4; mi++) {
        #pragma unroll
        for (int h = 0; h < 2; h++) {
            int rloc = m0 + mi * 16 + grp + h * 8;
            int grow = rowbase + rloc;
            unsigned char labi = (unsigned char)smc[SM_LABR + rloc];
            float full = 0.f, sme = 0.f, Sa = 0.f, mx = -1e30f;
            #pragma unroll
            for (int ni = 0; ni < 4; ni++) {
                #pragma unroll
                for (int u = 0; u < 2; u++) {
                    float x = acc[mi][ni][h * 2 + u] * TEMPC;
                    float y = x * 1.44269504f;
                    float tt = y + 12582912.f;
                    float fr = y - (tt - 12582912.f);
                    int ki = __float_as_int(tt) - 0x4B400000;
                    float pl = 0.00133336f;
                    pl = fmaf(pl, fr, 0.00961813f);
                    pl = fmaf(pl, fr, 0.05550411f);
                    pl = fmaf(pl, fr, 0.24022651f);
                    pl = fmaf(pl, fr, 0.69314718f);
                    pl = fmaf(pl, fr, 1.0f);
                    float e = pl * __int_as_float((ki + 127) << 23);
                    full += e;
                    int cloc = n0 + ni * 8 + t4 * 2 + u;
                    unsigned char lq = (unsigned char)smc[SM_LABC + cloc];
                    if (lq == labi) {
                        sme += e;
                        Sa = fmaf(wgt, x, Sa);
                        int j = colbase + cloc;
                        int pidx = (j & 63) + ((is2j && labi < KCLS) ? 64 : 0);
                        g_pos[grow][pidx] = x;
                    } else {
                        mx = fmaxf(mx, x);
                    }
                }
            }
            #pragma unroll
            for (int o = 1; o < 4; o <<= 1) {
                full += __shfl_xor_sync(0xffffffffu, full, o);
                sme  += __shfl_xor_sync(0xffffffffu, sme,  o);
                Sa   += __shfl_xor_sync(0xffffffffu, Sa,   o);
                mx = fmaxf(mx, __shfl_xor_sync(0xffffffffu, mx, o));
            }
            if (t4 == 0) {
                atomicAdd(&s_full[rloc], full);
                atomicAdd(&s_same[rloc], sme);
                atomicAdd(&s_S[rloc], Sa);
                atomicMax(&s_mx[rloc], encf(mx));
            }
        }
    }
    __syncthreads();
    if (tid < 128) {
        int grow = rowbase + tid;
        g_fullp[blockIdx.x][grow] = s_full[tid];
        g_samep[blockIdx.x][grow] = s_same[tid];
        g_Sp[blockIdx.x][grow]    = s_S[tid];
        g_mxp[blockIdx.x][grow]   = s_mx[tid];
    }
}

__global__ void k_rows(const unsigned char* __restrict__ ovraw,
                       float* out, int out_size) {
    __shared__ unsigned s_ovm;
    __shared__ float s_loss[128];
    __shared__ int   s_corr[128];
    __shared__ int   s_npk[128];
    int tid = threadIdx.x;
    int row = blockIdx.x * 128 + tid;
    if (tid == 0) s_ovm = sniff_ov(ovraw);
    __syncthreads();
    unsigned ovm = s_ovm;

    float full = 0.f, sme = 0.f, S = 0.f;
    unsigned mxe = 0u;
    #pragma unroll 8
    for (int b = 0; b < 32; b++) {
        full += g_fullp[b][row];
        sme  += g_samep[b][row];
        S    += g_Sp[b][row];
        mxe = max(mxe, g_mxp[b][row]);
    }
    int L = labelOf(row, ovm);
    bool ovl = (L < KCLS) ? ((ovm >> L) & 1u) : false;
    int cnt = ovl ? 128 : 64;
    int selfidx = (row & 63) + ((row >= NH && L < KCLS) ? 64 : 0);
    float xself = g_pos[row][selfidx];
    float negsum = full - sme;
    float Ss = S - xself;
    float W = ovl ? 95.0f : 63.0f;
    float mn = decf(mxe);
    int corr = 0;
    for (int t2 = 0; t2 < cnt; t2++)
        if (t2 != selfidx && g_pos[row][t2] > mn) corr++;

    s_loss[tid] = fmaf(W, logf(negsum), -Ss);
    s_corr[tid] = corr;
    s_npk[tid]  = cnt - 1;
    __syncthreads();
    for (int off = 64; off > 0; off >>= 1) {
        if (tid < off) {
            s_loss[tid] += s_loss[tid + off];
            s_corr[tid] += s_corr[tid + off];
            s_npk[tid]  += s_npk[tid + off];
        }
        __syncthreads();
    }
    if (tid == 0) {
        atomicAdd(&g_loss, s_loss[0]);
        atomicAdd(&g_corr, s_corr[0]);
        atomicAdd(&g_np, s_npk[0]);
        __threadfence();
        unsigned d = atomicAdd(&g_done, 1u);
        if (d == gridDim.x - 1) {
            __threadfence();
            float npf = (float)g_np;
            if (out_size >= 1) out[0] = (float)g_corr / npf;
            if (out_size >= 2) out[1] = g_loss / npf;
        }
    }
}

extern "C" void kernel_launch(void* const* d_in, const int* in_sizes, int n_in,
                              void* d_out, int out_size) {
    const float* f1 = nullptr;
    const float* f2 = nullptr;
    const unsigned char* ov = nullptr;
    for (int i = 0; i < n_in; i++) {
        if (in_sizes[i] == NH * FD) {
            if (!f1) f1 = (const float*)d_in[i];
            else if (!f2) f2 = (const float*)d_in[i];
        } else if (in_sizes[i] == KCLS) {
            ov = (const unsigned char*)d_in[i];
        }
    }
    cudaFuncSetAttribute(k_main, cudaFuncAttributeMaxDynamicSharedMemorySize, SM_TOTAL);

    k_main<<<dim3(32, 32), 256, SM_TOTAL>>>(f1, f2, ov);
    k_rows<<<32, 128>>>(ov, (float*)d_out, out_size);
}

// round 6
// speedup vs baseline: 3.7486x; 1.1199x over previous
#include <cuda_runtime.h>
#include <cuda_bf16.h>

// ContrastiveLoss on GB300 — 3-pass bf16-split mma.sync GEMM, 2 launches.
//   k_main : (unchanged from round 5, exact) 32x32 grid of 128x128 tiles,
//            2 CTAs/SM. Ahi*Bhi + Alo*Bhi + Ahi*Blo (B reloaded from L2).
//            Epilogue -> atomic-free partial arrays [colblock][row] + g_pos.
//   k_rows : REWRITTEN: one warp per row (512 blocks x 256 thr). Lane b
//            fetches partial b in parallel; warp-xor reduce; g_pos accuracy
//            scan distributed 4 entries/lane. Was 25.2us at occ 6% on 32
//            SMs; now all-SM, MLP-parallel.

#define NTOT 4096
#define NH   2048
#define FD   128
#define KCLS 32
#define TEMPC 0.01f

__device__ float         g_fullp[32][NTOT];
__device__ float         g_samep[32][NTOT];
__device__ float         g_Sp[32][NTOT];
__device__ unsigned int  g_mxp[32][NTOT];
__device__ float         g_pos[NTOT][128];
__device__ float         g_loss;
__device__ int           g_corr;
__device__ int           g_np;
__device__ unsigned int  g_done;

__device__ __forceinline__ unsigned int encf(float f) {
    unsigned int u = __float_as_uint(f);
    return (u & 0x80000000u) ? ~u : (u | 0x80000000u);
}
__device__ __forceinline__ float decf(unsigned int v) {
    unsigned int u = (v & 0x80000000u) ? (v & 0x7FFFFFFFu) : ~v;
    return __uint_as_float(u);
}

__device__ unsigned sniff_ov(const unsigned char* __restrict__ ovraw) {
    const unsigned* u32p = (const unsigned*)ovraw;
    bool allF = true, anyF = false;
    #pragma unroll
    for (int c = 0; c < 8; c++) {
        unsigned u = u32p[c];
        if (u != 0u && u != 0x3F800000u) allF = false;
        if (u == 0x3F800000u) anyF = true;
    }
    int mode;
    if (allF && anyF) mode = 2;
    else {
        bool oddNZ = false;
        for (int i = 0; i < 32; i++) if ((i & 3) && ovraw[i]) oddNZ = true;
        mode = oddNZ ? 0 : 1;
    }
    unsigned m = 0;
    for (int c = 0; c < 32; c++) {
        bool ov;
        if (mode == 0)      ov = ovraw[c] != 0;
        else if (mode == 1) ov = ((const int*)ovraw)[c] != 0;
        else                ov = ((const float*)ovraw)[c] != 0.f;
        m |= (ov ? 1u : 0u) << c;
    }
    return m;
}

__device__ __forceinline__ int labelOf(int i, unsigned ovm) {
    if (i < NH) return i >> 6;
    int c = (i - NH) >> 6;
    if ((ovm >> c) & 1u) return c;
    return KCLS + __popc((~ovm) & ((1u << c) - 1u));
}

// ---------------- helpers ----------------

__device__ __forceinline__ unsigned smem_u32(const void* p) {
    unsigned a;
    asm("{ .reg .u64 t; cvta.to.shared.u64 t, %1; cvt.u32.u64 %0, t; }"
        : "=r"(a) : "l"(p));
    return a;
}

#define LDSM4(r, a) \
    asm volatile("ldmatrix.sync.aligned.m8n8.x4.shared.b16 {%0,%1,%2,%3}, [%4];" \
        : "=r"((r)[0]), "=r"((r)[1]), "=r"((r)[2]), "=r"((r)[3]) : "r"(a))

#define MMA(c, a, b0, b1) \
    asm volatile("mma.sync.aligned.m16n8k16.row.col.f32.bf16.bf16.f32 " \
        "{%0,%1,%2,%3}, {%4,%5,%6,%7}, {%8,%9}, {%0,%1,%2,%3};" \
        : "+f"((c)[0]), "+f"((c)[1]), "+f"((c)[2]), "+f"((c)[3]) \
        : "r"((a)[0]), "r"((a)[1]), "r"((a)[2]), "r"((a)[3]), "r"(b0), "r"(b1))

__device__ __forceinline__ unsigned pack2(float a, float b) {
    __nv_bfloat162 t = __floats2bfloat162_rn(a, b);
    return *(unsigned*)&t;
}

__device__ __forceinline__ unsigned swz(int row, int kq) {
    return (unsigned)row * 256u
         + ((((unsigned)(kq >> 3)) ^ ((unsigned)row & 7u)) << 4)
         + (((unsigned)kq & 7u) << 1);
}

__device__ __forceinline__ void cvt_hilo(float4 v, uint2& hi, uint2& lo) {
    __nv_bfloat16 h0 = __float2bfloat16(v.x);
    __nv_bfloat16 h1 = __float2bfloat16(v.y);
    __nv_bfloat16 h2 = __float2bfloat16(v.z);
    __nv_bfloat16 h3 = __float2bfloat16(v.w);
    __nv_bfloat162 t01; t01.x = h0; t01.y = h1;
    __nv_bfloat162 t23; t23.x = h2; t23.y = h3;
    hi = make_uint2(*(unsigned*)&t01, *(unsigned*)&t23);
    lo = make_uint2(pack2(v.x - __bfloat162float(h0), v.y - __bfloat162float(h1)),
                    pack2(v.z - __bfloat162float(h2), v.w - __bfloat162float(h3)));
}

// ---------------- main kernel ----------------

#define SM_AHI  0
#define SM_ALO  32768
#define SM_B    65536
#define SM_LABC 98304
#define SM_LABR 98432
#define SM_RED  98560
#define SM_TOTAL (98560 + 4 * 512)

__global__ void __launch_bounds__(256, 2)
k_main(const float* __restrict__ f1, const float* __restrict__ f2,
       const unsigned char* __restrict__ ovraw) {
    extern __shared__ char smc[];
    unsigned sbase = smem_u32(smc);
    float* s_full = (float*)(smc + SM_RED);
    float* s_same = s_full + 128;
    float* s_S    = s_same + 128;
    unsigned* s_mx = (unsigned*)(s_S + 128);
    __shared__ unsigned s_ovm;

    const int tid = threadIdx.x, wid = tid >> 5, lane = tid & 31;
    const int rowbase = blockIdx.y << 7, colbase = blockIdx.x << 7;
    const int m0 = (wid >> 2) << 6;      // 0 or 64
    const int n0 = (wid & 3) << 5;       // 0,32,64,96

    if (tid == 0) {
        s_ovm = sniff_ov(ovraw);
        if (blockIdx.x == 0 && blockIdx.y == 0) {
            g_loss = 0.f; g_corr = 0; g_np = 0; g_done = 0u;
        }
    }
    __syncthreads();
    const unsigned ovm = s_ovm;

    if (tid < 128) {
        smc[SM_LABC + tid] = (char)labelOf(colbase + tid, ovm);
        smc[SM_LABR + tid] = (char)labelOf(rowbase + tid, ovm);
        s_full[tid] = 0.f; s_same[tid] = 0.f; s_S[tid] = 0.f; s_mx[tid] = 0u;
    }

    const float* Asrc = (rowbase < NH) ? f1 + (size_t)rowbase * FD
                                       : f2 + (size_t)(rowbase - NH) * FD;
    const float* Bsrc = (colbase < NH) ? f1 + (size_t)colbase * FD
                                       : f2 + (size_t)(colbase - NH) * FD;

    // Load A (hi+lo) and B (hi) into SMEM.
    #pragma unroll
    for (int it = 0; it < 16; ++it) {
        int idx = it * 256 + tid;                 // 4096 float4 slots
        int row = idx >> 5, kq = (idx & 31) << 2;
        unsigned so = swz(row, kq);
        uint2 hi, lo;
        cvt_hilo(*(const float4*)(Asrc + row * FD + kq), hi, lo);
        *(uint2*)(smc + SM_AHI + so) = hi;
        *(uint2*)(smc + SM_ALO + so) = lo;
        float4 vb = *(const float4*)(Bsrc + row * FD + kq);
        __nv_bfloat162 b01 = __floats2bfloat162_rn(vb.x, vb.y);
        __nv_bfloat162 b23 = __floats2bfloat162_rn(vb.z, vb.w);
        *(uint2*)(smc + SM_B + so) = make_uint2(*(unsigned*)&b01, *(unsigned*)&b23);
    }
    __syncthreads();

    const int rA  = ((lane >> 3) & 1) * 8 + (lane & 7);
    const int kbA = (lane >> 4) & 1;
    const int rB  = ((lane >> 4) & 1) * 8 + (lane & 7);
    const int kbB = (lane >> 3) & 1;
    const unsigned roA = (unsigned)(m0 + rA) * 256u;
    const unsigned roB = (unsigned)(n0 + rB) * 256u;

    float acc[4][4][4];
    #pragma unroll
    for (int mi = 0; mi < 4; mi++)
        #pragma unroll
        for (int ni = 0; ni < 4; ni++)
            #pragma unroll
            for (int u = 0; u < 4; u++) acc[mi][ni][u] = 0.f;

    // Pass 1: Ahi * Bhi ; Pass 2: Alo * Bhi
    #pragma unroll 1
    for (int pass = 0; pass < 2; ++pass) {
        const unsigned abase = (pass == 0) ? (sbase + SM_AHI) : (sbase + SM_ALO);
        #pragma unroll 4
        for (int ks = 0; ks < 8; ++ks) {
            unsigned aF[4][4], bF[2][4];
            unsigned chA = ((unsigned)((ks * 2 + kbA) ^ (rA & 7))) << 4;
            unsigned chB = ((unsigned)((ks * 2 + kbB) ^ (rB & 7))) << 4;
            #pragma unroll
            for (int mi = 0; mi < 4; mi++)
                LDSM4(aF[mi], abase + roA + (unsigned)(mi * 16) * 256u + chA);
            #pragma unroll
            for (int nj = 0; nj < 2; nj++)
                LDSM4(bF[nj], sbase + SM_B + roB + (unsigned)(nj * 16) * 256u + chB);
            #pragma unroll
            for (int mi = 0; mi < 4; mi++)
                #pragma unroll
                for (int ni = 0; ni < 4; ni++) {
                    int p = ni >> 1, s = (ni & 1) * 2;
                    MMA(acc[mi][ni], aF[mi], bF[p][s], bF[p][s + 1]);
                }
        }
    }

    // Swap B tile to lo (reload from L2).
    __syncthreads();
    #pragma unroll
    for (int it = 0; it < 16; ++it) {
        int idx = it * 256 + tid;
        int row = idx >> 5, kq = (idx & 31) << 2;
        uint2 hi, lo;
        cvt_hilo(*(const float4*)(Bsrc + row * FD + kq), hi, lo);
        *(uint2*)(smc + SM_B + swz(row, kq)) = lo;
    }
    __syncthreads();

    // Pass 3: Ahi * Blo
    #pragma unroll 4
    for (int ks = 0; ks < 8; ++ks) {
        unsigned aF[4][4], bF[2][4];
        unsigned chA = ((unsigned)((ks * 2 + kbA) ^ (rA & 7))) << 4;
        unsigned chB = ((unsigned)((ks * 2 + kbB) ^ (rB & 7))) << 4;
        #pragma unroll
        for (int mi = 0; mi < 4; mi++)
            LDSM4(aF[mi], sbase + SM_AHI + roA + (unsigned)(mi * 16) * 256u + chA);
        #pragma unroll
        for (int nj = 0; nj < 2; nj++)
            LDSM4(bF[nj], sbase + SM_B + roB + (unsigned)(nj * 16) * 256u + chB);
        #pragma unroll
        for (int mi = 0; mi < 4; mi++)
            #pragma unroll
            for (int ni = 0; ni < 4; ni++) {
                int p = ni >> 1, s = (ni & 1) * 2;
                MMA(acc[mi][ni], aF[mi], bF[p][s], bF[p][s + 1]);
            }
    }

    // ---------------- epilogue ----------------
    const bool is2i = rowbase >= NH, is2j = colbase >= NH;
    const float wgt = (is2i != is2j) ? 0.5f : 1.0f;
    const int grp = lane >> 2, t4 = lane & 3;

    #pragma unroll
    for (int mi = 0; mi < 4; mi++) {
        #pragma unroll
        for (int h = 0; h < 2; h++) {
            int rloc = m0 + mi * 16 + grp + h * 8;
            int grow = rowbase + rloc;
            unsigned char labi = (unsigned char)smc[SM_LABR + rloc];
            float full = 0.f, sme = 0.f, Sa = 0.f, mx = -1e30f;
            #pragma unroll
            for (int ni = 0; ni < 4; ni++) {
                #pragma unroll
                for (int u = 0; u < 2; u++) {
                    float x = acc[mi][ni][h * 2 + u] * TEMPC;
                    float y = x * 1.44269504f;
                    float tt = y + 12582912.f;
                    float fr = y - (tt - 12582912.f);
                    int ki = __float_as_int(tt) - 0x4B400000;
                    float pl = 0.00133336f;
                    pl = fmaf(pl, fr, 0.00961813f);
                    pl = fmaf(pl, fr, 0.05550411f);
                    pl = fmaf(pl, fr, 0.24022651f);
                    pl = fmaf(pl, fr, 0.69314718f);
                    pl = fmaf(pl, fr, 1.0f);
                    float e = pl * __int_as_float((ki + 127) << 23);
                    full += e;
                    int cloc = n0 + ni * 8 + t4 * 2 + u;
                    unsigned char lq = (unsigned char)smc[SM_LABC + cloc];
                    if (lq == labi) {
                        sme += e;
                        Sa = fmaf(wgt, x, Sa);
                        int j = colbase + cloc;
                        int pidx = (j & 63) + ((is2j && labi < KCLS) ? 64 : 0);
                        g_pos[grow][pidx] = x;
                    } else {
                        mx = fmaxf(mx, x);
                    }
                }
            }
            #pragma unroll
            for (int o = 1; o < 4; o <<= 1) {
                full += __shfl_xor_sync(0xffffffffu, full, o);
                sme  += __shfl_xor_sync(0xffffffffu, sme,  o);
                Sa   += __shfl_xor_sync(0xffffffffu, Sa,   o);
                mx = fmaxf(mx, __shfl_xor_sync(0xffffffffu, mx, o));
            }
            if (t4 == 0) {
                atomicAdd(&s_full[rloc], full);
                atomicAdd(&s_same[rloc], sme);
                atomicAdd(&s_S[rloc], Sa);
                atomicMax(&s_mx[rloc], encf(mx));
            }
        }
    }
    __syncthreads();
    if (tid < 128) {
        int grow = rowbase + tid;
        g_fullp[blockIdx.x][grow] = s_full[tid];
        g_samep[blockIdx.x][grow] = s_same[tid];
        g_Sp[blockIdx.x][grow]    = s_S[tid];
        g_mxp[blockIdx.x][grow]   = s_mx[tid];
    }
}

// ---------------- reduction kernel: one warp per row ----------------

__global__ void __launch_bounds__(256)
k_rows(const unsigned char* __restrict__ ovraw, float* out, int out_size) {
    __shared__ unsigned s_ovm;
    __shared__ float s_l[8];
    __shared__ int   s_c[8];
    __shared__ int   s_n[8];
    const int tid = threadIdx.x, lane = tid & 31, w = tid >> 5;
    if (tid == 0) s_ovm = sniff_ov(ovraw);
    __syncthreads();
    const unsigned ovm = s_ovm;
    const int row = blockIdx.x * 8 + w;

    // Lane b fetches partial column b — 4 parallel loads, then warp-reduce.
    float full = g_fullp[lane][row];
    float sme  = g_samep[lane][row];
    float S    = g_Sp[lane][row];
    unsigned mxe = g_mxp[lane][row];
    #pragma unroll
    for (int o = 16; o > 0; o >>= 1) {
        full += __shfl_xor_sync(0xffffffffu, full, o);
        sme  += __shfl_xor_sync(0xffffffffu, sme,  o);
        S    += __shfl_xor_sync(0xffffffffu, S,    o);
        mxe = max(mxe, __shfl_xor_sync(0xffffffffu, mxe, o));
    }

    const int L = labelOf(row, ovm);
    const bool ovl = (L < KCLS) ? ((ovm >> L) & 1u) : false;
    const int cnt = ovl ? 128 : 64;
    const int selfidx = (row & 63) + ((row >= NH && L < KCLS) ? 64 : 0);
    const float mn = decf(mxe);

    // Accuracy scan: 4 entries per lane (2 if cnt==64).
    int corr = 0;
    #pragma unroll
    for (int t2 = lane; t2 < 128; t2 += 32) {
        if (t2 < cnt) {
            float v = g_pos[row][t2];
            if (t2 != selfidx && v > mn) corr++;
        }
    }
    #pragma unroll
    for (int o = 16; o > 0; o >>= 1)
        corr += __shfl_xor_sync(0xffffffffu, corr, o);

    if (lane == 0) {
        float xself = g_pos[row][selfidx];
        float W = ovl ? 95.0f : 63.0f;
        s_l[w] = fmaf(W, logf(full - sme), -(S - xself));
        s_c[w] = corr;
        s_n[w] = cnt - 1;
    }
    __syncthreads();
    if (tid == 0) {
        float lt = 0.f; int ct = 0, nt = 0;
        #pragma unroll
        for (int i = 0; i < 8; i++) { lt += s_l[i]; ct += s_c[i]; nt += s_n[i]; }
        atomicAdd(&g_loss, lt);
        atomicAdd(&g_corr, ct);
        atomicAdd(&g_np, nt);
        __threadfence();
        unsigned d = atomicAdd(&g_done, 1u);
        if (d == gridDim.x - 1) {
            __threadfence();
            float npf = (float)g_np;
            if (out_size >= 1) out[0] = (float)g_corr / npf;
            if (out_size >= 2) out[1] = g_loss / npf;
        }
    }
}

extern "C" void kernel_launch(void* const* d_in, const int* in_sizes, int n_in,
                              void* d_out, int out_size) {
    const float* f1 = nullptr;
    const float* f2 = nullptr;
    const unsigned char* ov = nullptr;
    for (int i = 0; i < n_in; i++) {
        if (in_sizes[i] == NH * FD) {
            if (!f1) f1 = (const float*)d_in[i];
            else if (!f2) f2 = (const float*)d_in[i];
        } else if (in_sizes[i] == KCLS) {
            ov = (const unsigned char*)d_in[i];
        }
    }
    cudaFuncSetAttribute(k_main, cudaFuncAttributeMaxDynamicSharedMemorySize, SM_TOTAL);

    k_main<<<dim3(32, 32), 256, SM_TOTAL>>>(f1, f2, ov);
    k_rows<<<512, 256>>>(ov, (float*)d_out, out_size);
}

// round 7
// speedup vs baseline: 4.5424x; 1.2118x over previous
#include <cuda_runtime.h>
#include <cuda_bf16.h>

// ContrastiveLoss on GB300 — symmetric-triangular 3-pass bf16-split HMMA GEMM.
//   k_main : upper-triangle tiles only (bx>=by; 528 of 1024). Off-diag tiles
//            produce BOTH row stats (normal) and col stats (transposed tile's
//            row stats, reduced across grp lanes) in a 2-sweep epilogue.
//            3-pass exact split: (Ahi*Bhi + Alo*Bhi) fused per-ks, then B
//            reloaded as lo for Ahi*Blo. Partials packed float4 -> g_part
//            [row][colblock] for coalesced k_rows reads. g_pos scatter in
//            both directions.
//   k_rows : one warp per row; lane cb reads g_part[row][cb] (coalesced
//            float4); warp reduce; distributed accuracy scan; done-counter
//            writes out[].

#define NTOT 4096
#define NH   2048
#define FD   128
#define KCLS 32
#define TEMPC 0.01f

__device__ float4        g_part[NTOT][32];   // x=full y=same z=S w=mxenc(bits)
__device__ float         g_pos[NTOT][128];
__device__ float         g_loss;
__device__ int           g_corr;
__device__ int           g_np;
__device__ unsigned int  g_done;

__device__ __forceinline__ unsigned int encf(float f) {
    unsigned int u = __float_as_uint(f);
    return (u & 0x80000000u) ? ~u : (u | 0x80000000u);
}
__device__ __forceinline__ float decf(unsigned int v) {
    unsigned int u = (v & 0x80000000u) ? (v & 0x7FFFFFFFu) : ~v;
    return __uint_as_float(u);
}

__device__ unsigned sniff_ov(const unsigned char* __restrict__ ovraw) {
    const unsigned* u32p = (const unsigned*)ovraw;
    bool allF = true, anyF = false;
    #pragma unroll
    for (int c = 0; c < 8; c++) {
        unsigned u = u32p[c];
        if (u != 0u && u != 0x3F800000u) allF = false;
        if (u == 0x3F800000u) anyF = true;
    }
    int mode;
    if (allF && anyF) mode = 2;
    else {
        bool oddNZ = false;
        for (int i = 0; i < 32; i++) if ((i & 3) && ovraw[i]) oddNZ = true;
        mode = oddNZ ? 0 : 1;
    }
    unsigned m = 0;
    for (int c = 0; c < 32; c++) {
        bool ov;
        if (mode == 0)      ov = ovraw[c] != 0;
        else if (mode == 1) ov = ((const int*)ovraw)[c] != 0;
        else                ov = ((const float*)ovraw)[c] != 0.f;
        m |= (ov ? 1u : 0u) << c;
    }
    return m;
}

__device__ __forceinline__ int labelOf(int i, unsigned ovm) {
    if (i < NH) return i >> 6;
    int c = (i - NH) >> 6;
    if ((ovm >> c) & 1u) return c;
    return KCLS + __popc((~ovm) & ((1u << c) - 1u));
}

// ---------------- helpers ----------------

__device__ __forceinline__ unsigned smem_u32(const void* p) {
    unsigned a;
    asm("{ .reg .u64 t; cvta.to.shared.u64 t, %1; cvt.u32.u64 %0, t; }"
        : "=r"(a) : "l"(p));
    return a;
}

#define LDSM4(r, a) \
    asm volatile("ldmatrix.sync.aligned.m8n8.x4.shared.b16 {%0,%1,%2,%3}, [%4];" \
        : "=r"((r)[0]), "=r"((r)[1]), "=r"((r)[2]), "=r"((r)[3]) : "r"(a))

#define MMA(c, a, b0, b1) \
    asm volatile("mma.sync.aligned.m16n8k16.row.col.f32.bf16.bf16.f32 " \
        "{%0,%1,%2,%3}, {%4,%5,%6,%7}, {%8,%9}, {%0,%1,%2,%3};" \
        : "+f"((c)[0]), "+f"((c)[1]), "+f"((c)[2]), "+f"((c)[3]) \
        : "r"((a)[0]), "r"((a)[1]), "r"((a)[2]), "r"((a)[3]), "r"(b0), "r"(b1))

__device__ __forceinline__ unsigned pack2(float a, float b) {
    __nv_bfloat162 t = __floats2bfloat162_rn(a, b);
    return *(unsigned*)&t;
}

__device__ __forceinline__ unsigned swz(int row, int kq) {
    return (unsigned)row * 256u
         + ((((unsigned)(kq >> 3)) ^ ((unsigned)row & 7u)) << 4)
         + (((unsigned)kq & 7u) << 1);
}

__device__ __forceinline__ void cvt_hilo(float4 v, uint2& hi, uint2& lo) {
    __nv_bfloat16 h0 = __float2bfloat16(v.x);
    __nv_bfloat16 h1 = __float2bfloat16(v.y);
    __nv_bfloat16 h2 = __float2bfloat16(v.z);
    __nv_bfloat16 h3 = __float2bfloat16(v.w);
    __nv_bfloat162 t01; t01.x = h0; t01.y = h1;
    __nv_bfloat162 t23; t23.x = h2; t23.y = h3;
    hi = make_uint2(*(unsigned*)&t01, *(unsigned*)&t23);
    lo = make_uint2(pack2(v.x - __bfloat162float(h0), v.y - __bfloat162float(h1)),
                    pack2(v.z - __bfloat162float(h2), v.w - __bfloat162float(h3)));
}

__device__ __forceinline__ float exp_poly(float x, float& /*dummy*/) { return 0.f; }

__device__ __forceinline__ float fast_exp(float x) {
    float y = x * 1.44269504f;
    float tt = y + 12582912.f;
    float fr = y - (tt - 12582912.f);
    int ki = __float_as_int(tt) - 0x4B400000;
    float pl = 0.00133336f;
    pl = fmaf(pl, fr, 0.00961813f);
    pl = fmaf(pl, fr, 0.05550411f);
    pl = fmaf(pl, fr, 0.24022651f);
    pl = fmaf(pl, fr, 0.69314718f);
    pl = fmaf(pl, fr, 1.0f);
    return pl * __int_as_float((ki + 127) << 23);
}

// ---------------- main kernel ----------------

#define SM_AHI  0
#define SM_ALO  32768
#define SM_B    65536
#define SM_LABC 98304
#define SM_LABR 98432
#define SM_RED  98560                   // row arrays: 4 x 512B
#define SM_RED2 (98560 + 2048)          // col arrays: 4 x 512B
#define SM_TOTAL (98560 + 4096)

__global__ void __launch_bounds__(256, 2)
k_main(const float* __restrict__ f1, const float* __restrict__ f2,
       const unsigned char* __restrict__ ovraw) {
    const int bx = blockIdx.x, by = blockIdx.y;
    if (bx < by) return;                         // upper triangle only
    const bool diag = (bx == by);

    extern __shared__ char smc[];
    unsigned sbase = smem_u32(smc);
    float* s_full = (float*)(smc + SM_RED);
    float* s_same = s_full + 128;
    float* s_S    = s_same + 128;
    unsigned* s_mx = (unsigned*)(s_S + 128);
    float* c_full = (float*)(smc + SM_RED2);
    float* c_same = c_full + 128;
    float* c_S    = c_same + 128;
    unsigned* c_mx = (unsigned*)(c_S + 128);
    __shared__ unsigned s_ovm;

    const int tid = threadIdx.x, wid = tid >> 5, lane = tid & 31;
    const int rowbase = by << 7, colbase = bx << 7;
    const int m0 = (wid >> 2) << 6;
    const int n0 = (wid & 3) << 5;

    if (tid == 0) {
        s_ovm = sniff_ov(ovraw);
        if (bx == 0 && by == 0) { g_loss = 0.f; g_corr = 0; g_np = 0; g_done = 0u; }
    }
    __syncthreads();
    const unsigned ovm = s_ovm;

    if (tid < 128) {
        smc[SM_LABC + tid] = (char)labelOf(colbase + tid, ovm);
        smc[SM_LABR + tid] = (char)labelOf(rowbase + tid, ovm);
        s_full[tid] = 0.f; s_same[tid] = 0.f; s_S[tid] = 0.f; s_mx[tid] = 0u;
        c_full[tid] = 0.f; c_same[tid] = 0.f; c_S[tid] = 0.f; c_mx[tid] = 0u;
    }

    const float* Asrc = (rowbase < NH) ? f1 + (size_t)rowbase * FD
                                       : f2 + (size_t)(rowbase - NH) * FD;
    const float* Bsrc = (colbase < NH) ? f1 + (size_t)colbase * FD
                                       : f2 + (size_t)(colbase - NH) * FD;

    #pragma unroll
    for (int it = 0; it < 16; ++it) {
        int idx = it * 256 + tid;
        int row = idx >> 5, kq = (idx & 31) << 2;
        unsigned so = swz(row, kq);
        uint2 hi, lo;
        cvt_hilo(*(const float4*)(Asrc + row * FD + kq), hi, lo);
        *(uint2*)(smc + SM_AHI + so) = hi;
        *(uint2*)(smc + SM_ALO + so) = lo;
        float4 vb = *(const float4*)(Bsrc + row * FD + kq);
        __nv_bfloat162 b01 = __floats2bfloat162_rn(vb.x, vb.y);
        __nv_bfloat162 b23 = __floats2bfloat162_rn(vb.z, vb.w);
        *(uint2*)(smc + SM_B + so) = make_uint2(*(unsigned*)&b01, *(unsigned*)&b23);
    }
    __syncthreads();

    const int rA  = ((lane >> 3) & 1) * 8 + (lane & 7);
    const int kbA = (lane >> 4) & 1;
    const int rB  = ((lane >> 4) & 1) * 8 + (lane & 7);
    const int kbB = (lane >> 3) & 1;
    const unsigned roA = (unsigned)(m0 + rA) * 256u;
    const unsigned roB = (unsigned)(n0 + rB) * 256u;

    float acc[4][4][4];
    #pragma unroll
    for (int mi = 0; mi < 4; mi++)
        #pragma unroll
        for (int ni = 0; ni < 4; ni++)
            #pragma unroll
            for (int u = 0; u < 4; u++) acc[mi][ni][u] = 0.f;

    // Fused passes 1+2: (Ahi + Alo) * Bhi — B fragments loaded once per ks.
    #pragma unroll 2
    for (int ks = 0; ks < 8; ++ks) {
        unsigned chA = ((unsigned)((ks * 2 + kbA) ^ (rA & 7))) << 4;
        unsigned chB = ((unsigned)((ks * 2 + kbB) ^ (rB & 7))) << 4;
        unsigned bF[2][4];
        #pragma unroll
        for (int nj = 0; nj < 2; nj++)
            LDSM4(bF[nj], sbase + SM_B + roB + (unsigned)(nj * 16) * 256u + chB);
        #pragma unroll
        for (int mi = 0; mi < 4; mi++) {
            unsigned aH[4], aL[4];
            LDSM4(aH, sbase + SM_AHI + roA + (unsigned)(mi * 16) * 256u + chA);
            LDSM4(aL, sbase + SM_ALO + roA + (unsigned)(mi * 16) * 256u + chA);
            #pragma unroll
            for (int ni = 0; ni < 4; ni++) {
                int p = ni >> 1, s = (ni & 1) * 2;
                MMA(acc[mi][ni], aH, bF[p][s], bF[p][s + 1]);
                MMA(acc[mi][ni], aL, bF[p][s], bF[p][s + 1]);
            }
        }
    }

    // Swap B tile to lo.
    __syncthreads();
    #pragma unroll
    for (int it = 0; it < 16; ++it) {
        int idx = it * 256 + tid;
        int row = idx >> 5, kq = (idx & 31) << 2;
        uint2 hi, lo;
        cvt_hilo(*(const float4*)(Bsrc + row * FD + kq), hi, lo);
        *(uint2*)(smc + SM_B + swz(row, kq)) = lo;
    }
    __syncthreads();

    // Pass 3: Ahi * Blo
    #pragma unroll 2
    for (int ks = 0; ks < 8; ++ks) {
        unsigned chA = ((unsigned)((ks * 2 + kbA) ^ (rA & 7))) << 4;
        unsigned chB = ((unsigned)((ks * 2 + kbB) ^ (rB & 7))) << 4;
        unsigned bF[2][4];
        #pragma unroll
        for (int nj = 0; nj < 2; nj++)
            LDSM4(bF[nj], sbase + SM_B + roB + (unsigned)(nj * 16) * 256u + chB);
        #pragma unroll
        for (int mi = 0; mi < 4; mi++) {
            unsigned aH[4];
            LDSM4(aH, sbase + SM_AHI + roA + (unsigned)(mi * 16) * 256u + chA);
            #pragma unroll
            for (int ni = 0; ni < 4; ni++) {
                int p = ni >> 1, s = (ni & 1) * 2;
                MMA(acc[mi][ni], aH, bF[p][s], bF[p][s + 1]);
            }
        }
    }

    // ---------------- epilogue sweep 1: row stats ----------------
    const bool is2i = rowbase >= NH, is2j = colbase >= NH;
    const float wgt = (is2i != is2j) ? 0.5f : 1.0f;
    const int grp = lane >> 2, t4 = lane & 3;

    #pragma unroll
    for (int mi = 0; mi < 4; mi++) {
        #pragma unroll
        for (int h = 0; h < 2; h++) {
            int rloc = m0 + mi * 16 + grp + h * 8;
            int grow = rowbase + rloc;
            unsigned char labi = (unsigned char)smc[SM_LABR + rloc];
            float full = 0.f, sme = 0.f, Sa = 0.f, mx = -1e30f;
            #pragma unroll
            for (int ni = 0; ni < 4; ni++) {
                #pragma unroll
                for (int u = 0; u < 2; u++) {
                    float x = acc[mi][ni][h * 2 + u] * TEMPC;
                    float e = fast_exp(x);
                    full += e;
                    int cloc = n0 + ni * 8 + t4 * 2 + u;
                    unsigned char lq = (unsigned char)smc[SM_LABC + cloc];
                    if (lq == labi) {
                        sme += e;
                        Sa = fmaf(wgt, x, Sa);
                        int j = colbase + cloc;
                        int pidx = (j & 63) + ((is2j && labi < KCLS) ? 64 : 0);
                        g_pos[grow][pidx] = x;
                    } else {
                        mx = fmaxf(mx, x);
                    }
                }
            }
            #pragma unroll
            for (int o = 1; o < 4; o <<= 1) {
                full += __shfl_xor_sync(0xffffffffu, full, o);
                sme  += __shfl_xor_sync(0xffffffffu, sme,  o);
                Sa   += __shfl_xor_sync(0xffffffffu, Sa,   o);
                mx = fmaxf(mx, __shfl_xor_sync(0xffffffffu, mx, o));
            }
            if (t4 == 0) {
                atomicAdd(&s_full[rloc], full);
                atomicAdd(&s_same[rloc], sme);
                atomicAdd(&s_S[rloc], Sa);
                atomicMax(&s_mx[rloc], encf(mx));
            }
        }
    }

    // ---------------- epilogue sweep 2: col stats (off-diag only) ----------
    if (!diag) {
        #pragma unroll
        for (int ni = 0; ni < 4; ni++) {
            float cf[2] = {0.f, 0.f}, cs[2] = {0.f, 0.f}, cS2[2] = {0.f, 0.f};
            float cm[2] = {-1e30f, -1e30f};
            #pragma unroll
            for (int mi = 0; mi < 4; mi++) {
                #pragma unroll
                for (int h = 0; h < 2; h++) {
                    int rloc = m0 + mi * 16 + grp + h * 8;
                    int grow = rowbase + rloc;
                    unsigned char labi = (unsigned char)smc[SM_LABR + rloc];
                    int pidx2 = (grow & 63) + ((is2i && labi < KCLS) ? 64 : 0);
                    #pragma unroll
                    for (int u = 0; u < 2; u++) {
                        float x = acc[mi][ni][h * 2 + u] * TEMPC;
                        float e = fast_exp(x);
                        cf[u] += e;
                        int cloc = n0 + ni * 8 + t4 * 2 + u;
                        unsigned char lq = (unsigned char)smc[SM_LABC + cloc];
                        if (lq == labi) {
                            cs[u] += e;
                            cS2[u] = fmaf(wgt, x, cS2[u]);
                            g_pos[colbase + cloc][pidx2] = x;
                        } else {
                            cm[u] = fmaxf(cm[u], x);
                        }
                    }
                }
            }
            #pragma unroll
            for (int u = 0; u < 2; u++) {
                #pragma unroll
                for (int o = 4; o < 32; o <<= 1) {
                    cf[u]  += __shfl_xor_sync(0xffffffffu, cf[u],  o);
                    cs[u]  += __shfl_xor_sync(0xffffffffu, cs[u],  o);
                    cS2[u] += __shfl_xor_sync(0xffffffffu, cS2[u], o);
                    cm[u] = fmaxf(cm[u], __shfl_xor_sync(0xffffffffu, cm[u], o));
                }
                if (grp == 0) {
                    int cloc = n0 + ni * 8 + t4 * 2 + u;
                    atomicAdd(&c_full[cloc], cf[u]);
                    atomicAdd(&c_same[cloc], cs[u]);
                    atomicAdd(&c_S[cloc], cS2[u]);
                    atomicMax(&c_mx[cloc], encf(cm[u]));
                }
            }
        }
    }

    __syncthreads();
    if (tid < 128) {
        g_part[rowbase + tid][bx] = make_float4(s_full[tid], s_same[tid], s_S[tid],
                                                __uint_as_float(s_mx[tid]));
        if (!diag)
            g_part[colbase + tid][by] = make_float4(c_full[tid], c_same[tid], c_S[tid],
                                                    __uint_as_float(c_mx[tid]));
    }
}

// ---------------- reduction kernel: one warp per row ----------------

__global__ void __launch_bounds__(256)
k_rows(const unsigned char* __restrict__ ovraw, float* out, int out_size) {
    __shared__ unsigned s_ovm;
    __shared__ float s_l[8];
    __shared__ int   s_c[8];
    __shared__ int   s_n[8];
    const int tid = threadIdx.x, lane = tid & 31, w = tid >> 5;
    if (tid == 0) s_ovm = sniff_ov(ovraw);
    __syncthreads();
    const unsigned ovm = s_ovm;
    const int row = blockIdx.x * 8 + w;

    float4 p = g_part[row][lane];     // coalesced: 512B per warp
    float full = p.x, sme = p.y, S = p.z;
    unsigned mxe = __float_as_uint(p.w);
    #pragma unroll
    for (int o = 16; o > 0; o >>= 1) {
        full += __shfl_xor_sync(0xffffffffu, full, o);
        sme  += __shfl_xor_sync(0xffffffffu, sme,  o);
        S    += __shfl_xor_sync(0xffffffffu, S,    o);
        mxe = max(mxe, __shfl_xor_sync(0xffffffffu, mxe, o));
    }

    const int L = labelOf(row, ovm);
    const bool ovl = (L < KCLS) ? ((ovm >> L) & 1u) : false;
    const int cnt = ovl ? 128 : 64;
    const int selfidx = (row & 63) + ((row >= NH && L < KCLS) ? 64 : 0);
    const float mn = decf(mxe);

    int corr = 0;
    #pragma unroll
    for (int t2 = lane; t2 < 128; t2 += 32) {
        if (t2 < cnt) {
            float v = g_pos[row][t2];
            if (t2 != selfidx && v > mn) corr++;
        }
    }
    #pragma unroll
    for (int o = 16; o > 0; o >>= 1)
        corr += __shfl_xor_sync(0xffffffffu, corr, o);

    if (lane == 0) {
        float xself = g_pos[row][selfidx];
        float W = ovl ? 95.0f : 63.0f;
        s_l[w] = fmaf(W, logf(full - sme), -(S - xself));
        s_c[w] = corr;
        s_n[w] = cnt - 1;
    }
    __syncthreads();
    if (tid == 0) {
        float lt = 0.f; int ct = 0, nt = 0;
        #pragma unroll
        for (int i = 0; i < 8; i++) { lt += s_l[i]; ct += s_c[i]; nt += s_n[i]; }
        atomicAdd(&g_loss, lt);
        atomicAdd(&g_corr, ct);
        atomicAdd(&g_np, nt);
        __threadfence();
        unsigned d = atomicAdd(&g_done, 1u);
        if (d == gridDim.x - 1) {
            __threadfence();
            float npf = (float)g_np;
            if (out_size >= 1) out[0] = (float)g_corr / npf;
            if (out_size >= 2) out[1] = g_loss / npf;
        }
    }
}

extern "C" void kernel_launch(void* const* d_in, const int* in_sizes, int n_in,
                              void* d_out, int out_size) {
    const float* f1 = nullptr;
    const float* f2 = nullptr;
    const unsigned char* ov = nullptr;
    for (int i = 0; i < n_in; i++) {
        if (in_sizes[i] == NH * FD) {
            if (!f1) f1 = (const float*)d_in[i];
            else if (!f2) f2 = (const float*)d_in[i];
        } else if (in_sizes[i] == KCLS) {
            ov = (const unsigned char*)d_in[i];
        }
    }
    cudaFuncSetAttribute(k_main, cudaFuncAttributeMaxDynamicSharedMemorySize, SM_TOTAL);

    k_main<<<dim3(32, 32), 256, SM_TOTAL>>>(f1, f2, ov);
    k_rows<<<512, 256>>>(ov, (float*)d_out, out_size);
}

// round 9
// speedup vs baseline: 5.1901x; 1.1426x over previous
#include <cuda_runtime.h>
#include <cuda_bf16.h>

// ContrastiveLoss on GB300 — symmetric-triangular 3-pass bf16-split HMMA GEMM.
//   k_main : compact 1D grid of 528 upper-triangle tiles (decoded in-kernel).
//            3-pass exact split: (Ahi+Alo)*Bhi fused per-ks, then B reloaded
//            as lo for Ahi*Blo. FUSED epilogue on off-diag tiles: one sweep
//            computes exp once and accumulates BOTH row stats (regs, t4-lane
//            reduce) and col stats (regs per ni, grp-lane reduce) -> smem
//            atomics -> packed float4 partials g_part[row][colblock].
//            g_pos scatter in both directions.
//   k_rows : one warp per row; coalesced float4 partial reads; warp reduce;
//            distributed accuracy scan; done-counter writes out[].

#define NTOT 4096
#define NH   2048
#define FD   128
#define KCLS 32
#define TEMPC 0.01f

__device__ float4        g_part[NTOT][32];   // x=full y=same z=S w=mxenc(bits)
__device__ float         g_pos[NTOT][128];
__device__ float         g_loss;
__device__ int           g_corr;
__device__ int           g_np;
__device__ unsigned int  g_done;

__device__ __forceinline__ unsigned int encf(float f) {
    unsigned int u = __float_as_uint(f);
    return (u & 0x80000000u) ? ~u : (u | 0x80000000u);
}
__device__ __forceinline__ float decf(unsigned int v) {
    unsigned int u = (v & 0x80000000u) ? (v & 0x7FFFFFFFu) : ~v;
    return __uint_as_float(u);
}

__device__ unsigned sniff_ov(const unsigned char* __restrict__ ovraw) {
    const unsigned* u32p = (const unsigned*)ovraw;
    bool allF = true, anyF = false;
    #pragma unroll
    for (int c = 0; c < 8; c++) {
        unsigned u = u32p[c];
        if (u != 0u && u != 0x3F800000u) allF = false;
        if (u == 0x3F800000u) anyF = true;
    }
    int mode;
    if (allF && anyF) mode = 2;
    else {
        bool oddNZ = false;
        for (int i = 0; i < 32; i++) if ((i & 3) && ovraw[i]) oddNZ = true;
        mode = oddNZ ? 0 : 1;
    }
    unsigned m = 0;
    for (int c = 0; c < 32; c++) {
        bool ov;
        if (mode == 0)      ov = ovraw[c] != 0;
        else if (mode == 1) ov = ((const int*)ovraw)[c] != 0;
        else                ov = ((const float*)ovraw)[c] != 0.f;
        m |= (ov ? 1u : 0u) << c;
    }
    return m;
}

__device__ __forceinline__ int labelOf(int i, unsigned ovm) {
    if (i < NH) return i >> 6;
    int c = (i - NH) >> 6;
    if ((ovm >> c) & 1u) return c;
    return KCLS + __popc((~ovm) & ((1u << c) - 1u));
}

// ---------------- helpers ----------------

__device__ __forceinline__ unsigned smem_u32(const void* p) {
    unsigned a;
    asm("{ .reg .u64 t; cvta.to.shared.u64 t, %1; cvt.u32.u64 %0, t; }"
        : "=r"(a) : "l"(p));
    return a;
}

#define LDSM4(r, a) \
    asm volatile("ldmatrix.sync.aligned.m8n8.x4.shared.b16 {%0,%1,%2,%3}, [%4];" \
        : "=r"((r)[0]), "=r"((r)[1]), "=r"((r)[2]), "=r"((r)[3]) : "r"(a))

#define MMA(c, a, b0, b1) \
    asm volatile("mma.sync.aligned.m16n8k16.row.col.f32.bf16.bf16.f32 " \
        "{%0,%1,%2,%3}, {%4,%5,%6,%7}, {%8,%9}, {%0,%1,%2,%3};" \
        : "+f"((c)[0]), "+f"((c)[1]), "+f"((c)[2]), "+f"((c)[3]) \
        : "r"((a)[0]), "r"((a)[1]), "r"((a)[2]), "r"((a)[3]), "r"(b0), "r"(b1))

__device__ __forceinline__ unsigned pack2(float a, float b) {
    __nv_bfloat162 t = __floats2bfloat162_rn(a, b);
    return *(unsigned*)&t;
}

__device__ __forceinline__ unsigned swz(int row, int kq) {
    return (unsigned)row * 256u
         + ((((unsigned)(kq >> 3)) ^ ((unsigned)row & 7u)) << 4)
         + (((unsigned)kq & 7u) << 1);
}

__device__ __forceinline__ void cvt_hilo(float4 v, uint2& hi, uint2& lo) {
    __nv_bfloat16 h0 = __float2bfloat16(v.x);
    __nv_bfloat16 h1 = __float2bfloat16(v.y);
    __nv_bfloat16 h2 = __float2bfloat16(v.z);
    __nv_bfloat16 h3 = __float2bfloat16(v.w);
    __nv_bfloat162 t01; t01.x = h0; t01.y = h1;
    __nv_bfloat162 t23; t23.x = h2; t23.y = h3;
    hi = make_uint2(*(unsigned*)&t01, *(unsigned*)&t23);
    lo = make_uint2(pack2(v.x - __bfloat162float(h0), v.y - __bfloat162float(h1)),
                    pack2(v.z - __bfloat162float(h2), v.w - __bfloat162float(h3)));
}

__device__ __forceinline__ float fast_exp(float x) {
    float y = x * 1.44269504f;
    float tt = y + 12582912.f;
    float fr = y - (tt - 12582912.f);
    int ki = __float_as_int(tt) - 0x4B400000;
    float pl = 0.00133336f;
    pl = fmaf(pl, fr, 0.00961813f);
    pl = fmaf(pl, fr, 0.05550411f);
    pl = fmaf(pl, fr, 0.24022651f);
    pl = fmaf(pl, fr, 0.69314718f);
    pl = fmaf(pl, fr, 1.0f);
    return pl * __int_as_float((ki + 127) << 23);
}

// ---------------- main kernel ----------------

#define SM_AHI  0
#define SM_ALO  32768
#define SM_B    65536
#define SM_LABC 98304
#define SM_LABR 98432
#define SM_RED  98560                   // row arrays: 4 x 512B
#define SM_RED2 (98560 + 2048)          // col arrays: 4 x 512B
#define SM_TOTAL (98560 + 4096)

__global__ void __launch_bounds__(256, 2)
k_main(const float* __restrict__ f1, const float* __restrict__ f2,
       const unsigned char* __restrict__ ovraw) {
    // Decode compact triangular index -> (bx, by) with bx >= by.
    int tt0 = blockIdx.x, by = 0;
    while (tt0 >= 32 - by) { tt0 -= 32 - by; by++; }
    const int bx = by + tt0;
    const bool diag = (bx == by);

    extern __shared__ char smc[];
    unsigned sbase = smem_u32(smc);
    float* s_full = (float*)(smc + SM_RED);
    float* s_same = s_full + 128;
    float* s_S    = s_same + 128;
    unsigned* s_mx = (unsigned*)(s_S + 128);
    float* c_full = (float*)(smc + SM_RED2);
    float* c_same = c_full + 128;
    float* c_S    = c_same + 128;
    unsigned* c_mx = (unsigned*)(c_S + 128);
    __shared__ unsigned s_ovm;

    const int tid = threadIdx.x, wid = tid >> 5, lane = tid & 31;
    const int rowbase = by << 7, colbase = bx << 7;
    const int m0 = (wid >> 2) << 6;
    const int n0 = (wid & 3) << 5;

    if (tid == 0) {
        s_ovm = sniff_ov(ovraw);
        if (blockIdx.x == 0) { g_loss = 0.f; g_corr = 0; g_np = 0; g_done = 0u; }
    }
    __syncthreads();
    const unsigned ovm = s_ovm;

    if (tid < 128) {
        smc[SM_LABC + tid] = (char)labelOf(colbase + tid, ovm);
        smc[SM_LABR + tid] = (char)labelOf(rowbase + tid, ovm);
        s_full[tid] = 0.f; s_same[tid] = 0.f; s_S[tid] = 0.f; s_mx[tid] = 0u;
        c_full[tid] = 0.f; c_same[tid] = 0.f; c_S[tid] = 0.f; c_mx[tid] = 0u;
    }

    const float* Asrc = (rowbase < NH) ? f1 + (size_t)rowbase * FD
                                       : f2 + (size_t)(rowbase - NH) * FD;
    const float* Bsrc = (colbase < NH) ? f1 + (size_t)colbase * FD
                                       : f2 + (size_t)(colbase - NH) * FD;

    #pragma unroll
    for (int it = 0; it < 16; ++it) {
        int idx = it * 256 + tid;
        int row = idx >> 5, kq = (idx & 31) << 2;
        unsigned so = swz(row, kq);
        uint2 hi, lo;
        cvt_hilo(*(const float4*)(Asrc + row * FD + kq), hi, lo);
        *(uint2*)(smc + SM_AHI + so) = hi;
        *(uint2*)(smc + SM_ALO + so) = lo;
        float4 vb = *(const float4*)(Bsrc + row * FD + kq);
        __nv_bfloat162 b01 = __floats2bfloat162_rn(vb.x, vb.y);
        __nv_bfloat162 b23 = __floats2bfloat162_rn(vb.z, vb.w);
        *(uint2*)(smc + SM_B + so) = make_uint2(*(unsigned*)&b01, *(unsigned*)&b23);
    }
    __syncthreads();

    const int rA  = ((lane >> 3) & 1) * 8 + (lane & 7);
    const int kbA = (lane >> 4) & 1;
    const int rB  = ((lane >> 4) & 1) * 8 + (lane & 7);
    const int kbB = (lane >> 3) & 1;
    const unsigned roA = (unsigned)(m0 + rA) * 256u;
    const unsigned roB = (unsigned)(n0 + rB) * 256u;

    float acc[4][4][4];
    #pragma unroll
    for (int mi = 0; mi < 4; mi++)
        #pragma unroll
        for (int ni = 0; ni < 4; ni++)
            #pragma unroll
            for (int u = 0; u < 4; u++) acc[mi][ni][u] = 0.f;

    // Fused passes 1+2: (Ahi + Alo) * Bhi.
    #pragma unroll 2
    for (int ks = 0; ks < 8; ++ks) {
        unsigned chA = ((unsigned)((ks * 2 + kbA) ^ (rA & 7))) << 4;
        unsigned chB = ((unsigned)((ks * 2 + kbB) ^ (rB & 7))) << 4;
        unsigned bF[2][4];
        #pragma unroll
        for (int nj = 0; nj < 2; nj++)
            LDSM4(bF[nj], sbase + SM_B + roB + (unsigned)(nj * 16) * 256u + chB);
        #pragma unroll
        for (int mi = 0; mi < 4; mi++) {
            unsigned aH[4], aL[4];
            LDSM4(aH, sbase + SM_AHI + roA + (unsigned)(mi * 16) * 256u + chA);
            LDSM4(aL, sbase + SM_ALO + roA + (unsigned)(mi * 16) * 256u + chA);
            #pragma unroll
            for (int ni = 0; ni < 4; ni++) {
                int p = ni >> 1, s = (ni & 1) * 2;
                MMA(acc[mi][ni], aH, bF[p][s], bF[p][s + 1]);
                MMA(acc[mi][ni], aL, bF[p][s], bF[p][s + 1]);
            }
        }
    }

    // Swap B tile to lo.
    __syncthreads();
    #pragma unroll
    for (int it = 0; it < 16; ++it) {
        int idx = it * 256 + tid;
        int row = idx >> 5, kq = (idx & 31) << 2;
        uint2 hi, lo;
        cvt_hilo(*(const float4*)(Bsrc + row * FD + kq), hi, lo);
        *(uint2*)(smc + SM_B + swz(row, kq)) = lo;
    }
    __syncthreads();

    // Pass 3: Ahi * Blo
    #pragma unroll 2
    for (int ks = 0; ks < 8; ++ks) {
        unsigned chA = ((unsigned)((ks * 2 + kbA) ^ (rA & 7))) << 4;
        unsigned chB = ((unsigned)((ks * 2 + kbB) ^ (rB & 7))) << 4;
        unsigned bF[2][4];
        #pragma unroll
        for (int nj = 0; nj < 2; nj++)
            LDSM4(bF[nj], sbase + SM_B + roB + (unsigned)(nj * 16) * 256u + chB);
        #pragma unroll
        for (int mi = 0; mi < 4; mi++) {
            unsigned aH[4];
            LDSM4(aH, sbase + SM_AHI + roA + (unsigned)(mi * 16) * 256u + chA);
            #pragma unroll
            for (int ni = 0; ni < 4; ni++) {
                int p = ni >> 1, s = (ni & 1) * 2;
                MMA(acc[mi][ni], aH, bF[p][s], bF[p][s + 1]);
            }
        }
    }

    // ---------------- epilogue ----------------
    const bool is2i = rowbase >= NH, is2j = colbase >= NH;
    const float wgt = (is2i != is2j) ? 0.5f : 1.0f;
    const int grp = lane >> 2, t4 = lane & 3;

    // Hoist row labels into registers.
    int labi[8];
    #pragma unroll
    for (int rj = 0; rj < 8; rj++)
        labi[rj] = (unsigned char)smc[SM_LABR + m0 + (rj >> 1) * 16 + grp + (rj & 1) * 8];

    if (diag) {
        // Row-only sweep.
        #pragma unroll
        for (int rj = 0; rj < 8; rj++) {
            int mi = rj >> 1, h = rj & 1;
            int rloc = m0 + mi * 16 + grp + h * 8;
            int grow = rowbase + rloc;
            float full = 0.f, sme = 0.f, Sa = 0.f, mx = -1e30f;
            #pragma unroll
            for (int ni = 0; ni < 4; ni++) {
                #pragma unroll
                for (int u = 0; u < 2; u++) {
                    float x = acc[mi][ni][h * 2 + u] * TEMPC;
                    float e = fast_exp(x);
                    full += e;
                    int cloc = n0 + ni * 8 + t4 * 2 + u;
                    int lq = (unsigned char)smc[SM_LABC + cloc];
                    if (lq == labi[rj]) {
                        sme += e;
                        Sa = fmaf(wgt, x, Sa);
                        int j = colbase + cloc;
                        int pidx = (j & 63) + ((is2j && labi[rj] < KCLS) ? 64 : 0);
                        g_pos[grow][pidx] = x;
                    } else {
                        mx = fmaxf(mx, x);
                    }
                }
            }
            #pragma unroll
            for (int o = 1; o < 4; o <<= 1) {
                full += __shfl_xor_sync(0xffffffffu, full, o);
                sme  += __shfl_xor_sync(0xffffffffu, sme,  o);
                Sa   += __shfl_xor_sync(0xffffffffu, Sa,   o);
                mx = fmaxf(mx, __shfl_xor_sync(0xffffffffu, mx, o));
            }
            if (t4 == 0) {
                atomicAdd(&s_full[rloc], full);
                atomicAdd(&s_same[rloc], sme);
                atomicAdd(&s_S[rloc], Sa);
                atomicMax(&s_mx[rloc], encf(mx));
            }
        }
    } else {
        // Fused row+col sweep: exp computed once per value.
        float rfull[8], rsme[8], rS[8], rmx[8];
        #pragma unroll
        for (int rj = 0; rj < 8; rj++) {
            rfull[rj] = 0.f; rsme[rj] = 0.f; rS[rj] = 0.f; rmx[rj] = -1e30f;
        }

        #pragma unroll
        for (int ni = 0; ni < 4; ni++) {
            float cf[2] = {0.f, 0.f}, cs[2] = {0.f, 0.f}, cS2[2] = {0.f, 0.f};
            float cm[2] = {-1e30f, -1e30f};
            int lq[2], cloc[2];
            #pragma unroll
            for (int u = 0; u < 2; u++) {
                cloc[u] = n0 + ni * 8 + t4 * 2 + u;
                lq[u] = (unsigned char)smc[SM_LABC + cloc[u]];
            }
            #pragma unroll
            for (int rj = 0; rj < 8; rj++) {
                int mi = rj >> 1, h = rj & 1;
                int rloc = m0 + mi * 16 + grp + h * 8;
                int grow = rowbase + rloc;
                int pidx2 = (grow & 63) + ((is2i && labi[rj] < KCLS) ? 64 : 0);
                #pragma unroll
                for (int u = 0; u < 2; u++) {
                    float x = acc[mi][ni][h * 2 + u] * TEMPC;
                    float e = fast_exp(x);
                    rfull[rj] += e;
                    cf[u] += e;
                    if (lq[u] == labi[rj]) {
                        rsme[rj] += e;
                        rS[rj] = fmaf(wgt, x, rS[rj]);
                        cs[u] += e;
                        cS2[u] = fmaf(wgt, x, cS2[u]);
                        int j = colbase + cloc[u];
                        int pidx = (j & 63) + ((is2j && labi[rj] < KCLS) ? 64 : 0);
                        g_pos[grow][pidx] = x;
                        g_pos[j][pidx2] = x;
                    } else {
                        rmx[rj] = fmaxf(rmx[rj], x);
                        cm[u] = fmaxf(cm[u], x);
                    }
                }
            }
            #pragma unroll
            for (int u = 0; u < 2; u++) {
                #pragma unroll
                for (int o = 4; o < 32; o <<= 1) {
                    cf[u]  += __shfl_xor_sync(0xffffffffu, cf[u],  o);
                    cs[u]  += __shfl_xor_sync(0xffffffffu, cs[u],  o);
                    cS2[u] += __shfl_xor_sync(0xffffffffu, cS2[u], o);
                    cm[u] = fmaxf(cm[u], __shfl_xor_sync(0xffffffffu, cm[u], o));
                }
                if (grp == 0) {
                    atomicAdd(&c_full[cloc[u]], cf[u]);
                    atomicAdd(&c_same[cloc[u]], cs[u]);
                    atomicAdd(&c_S[cloc[u]], cS2[u]);
                    atomicMax(&c_mx[cloc[u]], encf(cm[u]));
                }
            }
        }

        #pragma unroll
        for (int rj = 0; rj < 8; rj++) {
            int rloc = m0 + (rj >> 1) * 16 + grp + (rj & 1) * 8;
            float full = rfull[rj], sme = rsme[rj], Sa = rS[rj], mx = rmx[rj];
            #pragma unroll
            for (int o = 1; o < 4; o <<= 1) {
                full += __shfl_xor_sync(0xffffffffu, full, o);
                sme  += __shfl_xor_sync(0xffffffffu, sme,  o);
                Sa   += __shfl_xor_sync(0xffffffffu, Sa,   o);
                mx = fmaxf(mx, __shfl_xor_sync(0xffffffffu, mx, o));
            }
            if (t4 == 0) {
                atomicAdd(&s_full[rloc], full);
                atomicAdd(&s_same[rloc], sme);
                atomicAdd(&s_S[rloc], Sa);
                atomicMax(&s_mx[rloc], encf(mx));
            }
        }
    }

    __syncthreads();
    if (tid < 128) {
        g_part[rowbase + tid][bx] = make_float4(s_full[tid], s_same[tid], s_S[tid],
                                                __uint_as_float(s_mx[tid]));
        if (!diag)
            g_part[colbase + tid][by] = make_float4(c_full[tid], c_same[tid], c_S[tid],
                                                    __uint_as_float(c_mx[tid]));
    }
}

// ---------------- reduction kernel: one warp per row ----------------

__global__ void __launch_bounds__(256)
k_rows(const unsigned char* __restrict__ ovraw, float* out, int out_size) {
    __shared__ unsigned s_ovm;
    __shared__ float s_l[8];
    __shared__ int   s_c[8];
    __shared__ int   s_n[8];
    const int tid = threadIdx.x, lane = tid & 31, w = tid >> 5;
    if (tid == 0) s_ovm = sniff_ov(ovraw);
    __syncthreads();
    const unsigned ovm = s_ovm;
    const int row = blockIdx.x * 8 + w;

    float4 p = g_part[row][lane];
    float full = p.x, sme = p.y, S = p.z;
    unsigned mxe = __float_as_uint(p.w);
    #pragma unroll
    for (int o = 16; o > 0; o >>= 1) {
        full += __shfl_xor_sync(0xffffffffu, full, o);
        sme  += __shfl_xor_sync(0xffffffffu, sme,  o);
        S    += __shfl_xor_sync(0xffffffffu, S,    o);
        mxe = max(mxe, __shfl_xor_sync(0xffffffffu, mxe, o));
    }

    const int L = labelOf(row, ovm);
    const bool ovl = (L < KCLS) ? ((ovm >> L) & 1u) : false;
    const int cnt = ovl ? 128 : 64;
    const int selfidx = (row & 63) + ((row >= NH && L < KCLS) ? 64 : 0);
    const float mn = decf(mxe);

    int corr = 0;
    #pragma unroll
    for (int t2 = lane; t2 < 128; t2 += 32) {
        if (t2 < cnt) {
            float v = g_pos[row][t2];
            if (t2 != selfidx && v > mn) corr++;
        }
    }
    #pragma unroll
    for (int o = 16; o > 0; o >>= 1)
        corr += __shfl_xor_sync(0xffffffffu, corr, o);

    if (lane == 0) {
        float xself = g_pos[row][selfidx];
        float W = ovl ? 95.0f : 63.0f;
        s_l[w] = fmaf(W, logf(full - sme), -(S - xself));
        s_c[w] = corr;
        s_n[w] = cnt - 1;
    }
    __syncthreads();
    if (tid == 0) {
        float lt = 0.f; int ct = 0, nt = 0;
        #pragma unroll
        for (int i = 0; i < 8; i++) { lt += s_l[i]; ct += s_c[i]; nt += s_n[i]; }
        atomicAdd(&g_loss, lt);
        atomicAdd(&g_corr, ct);
        atomicAdd(&g_np, nt);
        __threadfence();
        unsigned d = atomicAdd(&g_done, 1u);
        if (d == gridDim.x - 1) {
            __threadfence();
            float npf = (float)g_np;
            if (out_size >= 1) out[0] = (float)g_corr / npf;
            if (out_size >= 2) out[1] = g_loss / npf;
        }
    }
}

extern "C" void kernel_launch(void* const* d_in, const int* in_sizes, int n_in,
                              void* d_out, int out_size) {
    const float* f1 = nullptr;
    const float* f2 = nullptr;
    const unsigned char* ov = nullptr;
    for (int i = 0; i < n_in; i++) {
        if (in_sizes[i] == NH * FD) {
            if (!f1) f1 = (const float*)d_in[i];
            else if (!f2) f2 = (const float*)d_in[i];
        } else if (in_sizes[i] == KCLS) {
            ov = (const unsigned char*)d_in[i];
        }
    }
    cudaFuncSetAttribute(k_main, cudaFuncAttributeMaxDynamicSharedMemorySize, SM_TOTAL);

    k_main<<<528, 256, SM_TOTAL>>>(f1, f2, ov);
    k_rows<<<512, 256>>>(ov, (float*)d_out, out_size);
}

// round 10
// speedup vs baseline: 5.2517x; 1.0119x over previous
#include <cuda_runtime.h>
#include <cuda_bf16.h>

// ContrastiveLoss on GB300 — symmetric-triangular 3-pass bf16-split HMMA GEMM.
//   k_main : compact 1D grid of 528 upper-triangle tiles. 3-pass exact split:
//            (Ahi+Alo)*Bhi fused per-ks, then B reloaded as lo for Ahi*Blo.
//            Fused epilogue (off-diag): exp computed ONCE per value via
//            MUFU ex2.approx (off the FMA pipe — comparisons use raw x, so
//            approx exp only perturbs sums at ~1e-6); accumulates row stats
//            (t4-lane reduce) and col stats (grp-lane reduce) -> smem atomics
//            -> packed float4 partials g_part[row][colblock]; g_pos scatter
//            both directions.
//   k_rows : one warp per row; coalesced float4 partial reads; warp reduce;
//            distributed accuracy scan; done-counter writes out[].

#define NTOT 4096
#define NH   2048
#define FD   128
#define KCLS 32
#define TEMPC 0.01f

__device__ float4        g_part[NTOT][32];   // x=full y=same z=S w=mxenc(bits)
__device__ float         g_pos[NTOT][128];
__device__ float         g_loss;
__device__ int           g_corr;
__device__ int           g_np;
__device__ unsigned int  g_done;

__device__ __forceinline__ unsigned int encf(float f) {
    unsigned int u = __float_as_uint(f);
    return (u & 0x80000000u) ? ~u : (u | 0x80000000u);
}
__device__ __forceinline__ float decf(unsigned int v) {
    unsigned int u = (v & 0x80000000u) ? (v & 0x7FFFFFFFu) : ~v;
    return __uint_as_float(u);
}

__device__ unsigned sniff_ov(const unsigned char* __restrict__ ovraw) {
    const unsigned* u32p = (const unsigned*)ovraw;
    bool allF = true, anyF = false;
    #pragma unroll
    for (int c = 0; c < 8; c++) {
        unsigned u = u32p[c];
        if (u != 0u && u != 0x3F800000u) allF = false;
        if (u == 0x3F800000u) anyF = true;
    }
    int mode;
    if (allF && anyF) mode = 2;
    else {
        bool oddNZ = false;
        for (int i = 0; i < 32; i++) if ((i & 3) && ovraw[i]) oddNZ = true;
        mode = oddNZ ? 0 : 1;
    }
    unsigned m = 0;
    for (int c = 0; c < 32; c++) {
        bool ov;
        if (mode == 0)      ov = ovraw[c] != 0;
        else if (mode == 1) ov = ((const int*)ovraw)[c] != 0;
        else                ov = ((const float*)ovraw)[c] != 0.f;
        m |= (ov ? 1u : 0u) << c;
    }
    return m;
}

__device__ __forceinline__ int labelOf(int i, unsigned ovm) {
    if (i < NH) return i >> 6;
    int c = (i - NH) >> 6;
    if ((ovm >> c) & 1u) return c;
    return KCLS + __popc((~ovm) & ((1u << c) - 1u));
}

// ---------------- helpers ----------------

__device__ __forceinline__ unsigned smem_u32(const void* p) {
    unsigned a;
    asm("{ .reg .u64 t; cvta.to.shared.u64 t, %1; cvt.u32.u64 %0, t; }"
        : "=r"(a) : "l"(p));
    return a;
}

#define LDSM4(r, a) \
    asm volatile("ldmatrix.sync.aligned.m8n8.x4.shared.b16 {%0,%1,%2,%3}, [%4];" \
        : "=r"((r)[0]), "=r"((r)[1]), "=r"((r)[2]), "=r"((r)[3]) : "r"(a))

#define MMA(c, a, b0, b1) \
    asm volatile("mma.sync.aligned.m16n8k16.row.col.f32.bf16.bf16.f32 " \
        "{%0,%1,%2,%3}, {%4,%5,%6,%7}, {%8,%9}, {%0,%1,%2,%3};" \
        : "+f"((c)[0]), "+f"((c)[1]), "+f"((c)[2]), "+f"((c)[3]) \
        : "r"((a)[0]), "r"((a)[1]), "r"((a)[2]), "r"((a)[3]), "r"(b0), "r"(b1))

__device__ __forceinline__ unsigned pack2(float a, float b) {
    __nv_bfloat162 t = __floats2bfloat162_rn(a, b);
    return *(unsigned*)&t;
}

__device__ __forceinline__ unsigned swz(int row, int kq) {
    return (unsigned)row * 256u
         + ((((unsigned)(kq >> 3)) ^ ((unsigned)row & 7u)) << 4)
         + (((unsigned)kq & 7u) << 1);
}

__device__ __forceinline__ void cvt_hilo(float4 v, uint2& hi, uint2& lo) {
    __nv_bfloat16 h0 = __float2bfloat16(v.x);
    __nv_bfloat16 h1 = __float2bfloat16(v.y);
    __nv_bfloat16 h2 = __float2bfloat16(v.z);
    __nv_bfloat16 h3 = __float2bfloat16(v.w);
    __nv_bfloat162 t01; t01.x = h0; t01.y = h1;
    __nv_bfloat162 t23; t23.x = h2; t23.y = h3;
    hi = make_uint2(*(unsigned*)&t01, *(unsigned*)&t23);
    lo = make_uint2(pack2(v.x - __bfloat162float(h0), v.y - __bfloat162float(h1)),
                    pack2(v.z - __bfloat162float(h2), v.w - __bfloat162float(h3)));
}

// MUFU-based exp: e^x = 2^(x*log2e). Comparisons never use e, only sums do;
// ex2.approx rel err ~2^-22 is invisible at the 1e-3 tolerance.
__device__ __forceinline__ float fast_exp(float x) {
    float r;
    asm("ex2.approx.ftz.f32 %0, %1;" : "=f"(r) : "f"(x * 1.44269504f));
    return r;
}

// ---------------- main kernel ----------------

#define SM_AHI  0
#define SM_ALO  32768
#define SM_B    65536
#define SM_LABC 98304
#define SM_LABR 98432
#define SM_RED  98560                   // row arrays: 4 x 512B
#define SM_RED2 (98560 + 2048)          // col arrays: 4 x 512B
#define SM_TOTAL (98560 + 4096)

__global__ void __launch_bounds__(256, 2)
k_main(const float* __restrict__ f1, const float* __restrict__ f2,
       const unsigned char* __restrict__ ovraw) {
    // Decode compact triangular index -> (bx, by) with bx >= by.
    int tt0 = blockIdx.x, by = 0;
    while (tt0 >= 32 - by) { tt0 -= 32 - by; by++; }
    const int bx = by + tt0;
    const bool diag = (bx == by);

    extern __shared__ char smc[];
    unsigned sbase = smem_u32(smc);
    float* s_full = (float*)(smc + SM_RED);
    float* s_same = s_full + 128;
    float* s_S    = s_same + 128;
    unsigned* s_mx = (unsigned*)(s_S + 128);
    float* c_full = (float*)(smc + SM_RED2);
    float* c_same = c_full + 128;
    float* c_S    = c_same + 128;
    unsigned* c_mx = (unsigned*)(c_S + 128);
    __shared__ unsigned s_ovm;

    const int tid = threadIdx.x, wid = tid >> 5, lane = tid & 31;
    const int rowbase = by << 7, colbase = bx << 7;
    const int m0 = (wid >> 2) << 6;
    const int n0 = (wid & 3) << 5;

    if (tid == 0) {
        s_ovm = sniff_ov(ovraw);
        if (blockIdx.x == 0) { g_loss = 0.f; g_corr = 0; g_np = 0; g_done = 0u; }
    }
    __syncthreads();
    const unsigned ovm = s_ovm;

    if (tid < 128) {
        smc[SM_LABC + tid] = (char)labelOf(colbase + tid, ovm);
        smc[SM_LABR + tid] = (char)labelOf(rowbase + tid, ovm);
        s_full[tid] = 0.f; s_same[tid] = 0.f; s_S[tid] = 0.f; s_mx[tid] = 0u;
        c_full[tid] = 0.f; c_same[tid] = 0.f; c_S[tid] = 0.f; c_mx[tid] = 0u;
    }

    const float* Asrc = (rowbase < NH) ? f1 + (size_t)rowbase * FD
                                       : f2 + (size_t)(rowbase - NH) * FD;
    const float* Bsrc = (colbase < NH) ? f1 + (size_t)colbase * FD
                                       : f2 + (size_t)(colbase - NH) * FD;

    #pragma unroll
    for (int it = 0; it < 16; ++it) {
        int idx = it * 256 + tid;
        int row = idx >> 5, kq = (idx & 31) << 2;
        unsigned so = swz(row, kq);
        uint2 hi, lo;
        cvt_hilo(*(const float4*)(Asrc + row * FD + kq), hi, lo);
        *(uint2*)(smc + SM_AHI + so) = hi;
        *(uint2*)(smc + SM_ALO + so) = lo;
        float4 vb = *(const float4*)(Bsrc + row * FD + kq);
        __nv_bfloat162 b01 = __floats2bfloat162_rn(vb.x, vb.y);
        __nv_bfloat162 b23 = __floats2bfloat162_rn(vb.z, vb.w);
        *(uint2*)(smc + SM_B + so) = make_uint2(*(unsigned*)&b01, *(unsigned*)&b23);
    }
    __syncthreads();

    const int rA  = ((lane >> 3) & 1) * 8 + (lane & 7);
    const int kbA = (lane >> 4) & 1;
    const int rB  = ((lane >> 4) & 1) * 8 + (lane & 7);
    const int kbB = (lane >> 3) & 1;
    const unsigned roA = (unsigned)(m0 + rA) * 256u;
    const unsigned roB = (unsigned)(n0 + rB) * 256u;

    float acc[4][4][4];
    #pragma unroll
    for (int mi = 0; mi < 4; mi++)
        #pragma unroll
        for (int ni = 0; ni < 4; ni++)
            #pragma unroll
            for (int u = 0; u < 4; u++) acc[mi][ni][u] = 0.f;

    // Fused passes 1+2: (Ahi + Alo) * Bhi.
    #pragma unroll 2
    for (int ks = 0; ks < 8; ++ks) {
        unsigned chA = ((unsigned)((ks * 2 + kbA) ^ (rA & 7))) << 4;
        unsigned chB = ((unsigned)((ks * 2 + kbB) ^ (rB & 7))) << 4;
        unsigned bF[2][4];
        #pragma unroll
        for (int nj = 0; nj < 2; nj++)
            LDSM4(bF[nj], sbase + SM_B + roB + (unsigned)(nj * 16) * 256u + chB);
        #pragma unroll
        for (int mi = 0; mi < 4; mi++) {
            unsigned aH[4], aL[4];
            LDSM4(aH, sbase + SM_AHI + roA + (unsigned)(mi * 16) * 256u + chA);
            LDSM4(aL, sbase + SM_ALO + roA + (unsigned)(mi * 16) * 256u + chA);
            #pragma unroll
            for (int ni = 0; ni < 4; ni++) {
                int p = ni >> 1, s = (ni & 1) * 2;
                MMA(acc[mi][ni], aH, bF[p][s], bF[p][s + 1]);
                MMA(acc[mi][ni], aL, bF[p][s], bF[p][s + 1]);
            }
        }
    }

    // Swap B tile to lo.
    __syncthreads();
    #pragma unroll
    for (int it = 0; it < 16; ++it) {
        int idx = it * 256 + tid;
        int row = idx >> 5, kq = (idx & 31) << 2;
        uint2 hi, lo;
        cvt_hilo(*(const float4*)(Bsrc + row * FD + kq), hi, lo);
        *(uint2*)(smc + SM_B + swz(row, kq)) = lo;
    }
    __syncthreads();

    // Pass 3: Ahi * Blo
    #pragma unroll 2
    for (int ks = 0; ks < 8; ++ks) {
        unsigned chA = ((unsigned)((ks * 2 + kbA) ^ (rA & 7))) << 4;
        unsigned chB = ((unsigned)((ks * 2 + kbB) ^ (rB & 7))) << 4;
        unsigned bF[2][4];
        #pragma unroll
        for (int nj = 0; nj < 2; nj++)
            LDSM4(bF[nj], sbase + SM_B + roB + (unsigned)(nj * 16) * 256u + chB);
        #pragma unroll
        for (int mi = 0; mi < 4; mi++) {
            unsigned aH[4];
            LDSM4(aH, sbase + SM_AHI + roA + (unsigned)(mi * 16) * 256u + chA);
            #pragma unroll
            for (int ni = 0; ni < 4; ni++) {
                int p = ni >> 1, s = (ni & 1) * 2;
                MMA(acc[mi][ni], aH, bF[p][s], bF[p][s + 1]);
            }
        }
    }

    // ---------------- epilogue ----------------
    const bool is2i = rowbase >= NH, is2j = colbase >= NH;
    const float wgt = (is2i != is2j) ? 0.5f : 1.0f;
    const int grp = lane >> 2, t4 = lane & 3;

    int labi[8];
    #pragma unroll
    for (int rj = 0; rj < 8; rj++)
        labi[rj] = (unsigned char)smc[SM_LABR + m0 + (rj >> 1) * 16 + grp + (rj & 1) * 8];

    if (diag) {
        #pragma unroll
        for (int rj = 0; rj < 8; rj++) {
            int mi = rj >> 1, h = rj & 1;
            int rloc = m0 + mi * 16 + grp + h * 8;
            int grow = rowbase + rloc;
            float full = 0.f, sme = 0.f, Sa = 0.f, mx = -1e30f;
            #pragma unroll
            for (int ni = 0; ni < 4; ni++) {
                #pragma unroll
                for (int u = 0; u < 2; u++) {
                    float x = acc[mi][ni][h * 2 + u] * TEMPC;
                    float e = fast_exp(x);
                    full += e;
                    int cloc = n0 + ni * 8 + t4 * 2 + u;
                    int lq = (unsigned char)smc[SM_LABC + cloc];
                    if (lq == labi[rj]) {
                        sme += e;
                        Sa = fmaf(wgt, x, Sa);
                        int j = colbase + cloc;
                        int pidx = (j & 63) + ((is2j && labi[rj] < KCLS) ? 64 : 0);
                        g_pos[grow][pidx] = x;
                    } else {
                        mx = fmaxf(mx, x);
                    }
                }
            }
            #pragma unroll
            for (int o = 1; o < 4; o <<= 1) {
                full += __shfl_xor_sync(0xffffffffu, full, o);
                sme  += __shfl_xor_sync(0xffffffffu, sme,  o);
                Sa   += __shfl_xor_sync(0xffffffffu, Sa,   o);
                mx = fmaxf(mx, __shfl_xor_sync(0xffffffffu, mx, o));
            }
            if (t4 == 0) {
                atomicAdd(&s_full[rloc], full);
                atomicAdd(&s_same[rloc], sme);
                atomicAdd(&s_S[rloc], Sa);
                atomicMax(&s_mx[rloc], encf(mx));
            }
        }
    } else {
        float rfull[8], rsme[8], rS[8], rmx[8];
        #pragma unroll
        for (int rj = 0; rj < 8; rj++) {
            rfull[rj] = 0.f; rsme[rj] = 0.f; rS[rj] = 0.f; rmx[rj] = -1e30f;
        }

        #pragma unroll
        for (int ni = 0; ni < 4; ni++) {
            float cf[2] = {0.f, 0.f}, cs[2] = {0.f, 0.f}, cS2[2] = {0.f, 0.f};
            float cm[2] = {-1e30f, -1e30f};
            int lq[2], cloc[2];
            #pragma unroll
            for (int u = 0; u < 2; u++) {
                cloc[u] = n0 + ni * 8 + t4 * 2 + u;
                lq[u] = (unsigned char)smc[SM_LABC + cloc[u]];
            }
            #pragma unroll
            for (int rj = 0; rj < 8; rj++) {
                int mi = rj >> 1, h = rj & 1;
                int rloc = m0 + mi * 16 + grp + h * 8;
                int grow = rowbase + rloc;
                int pidx2 = (grow & 63) + ((is2i && labi[rj] < KCLS) ? 64 : 0);
                #pragma unroll
                for (int u = 0; u < 2; u++) {
                    float x = acc[mi][ni][h * 2 + u] * TEMPC;
                    float e = fast_exp(x);
                    rfull[rj] += e;
                    cf[u] += e;
                    if (lq[u] == labi[rj]) {
                        rsme[rj] += e;
                        rS[rj] = fmaf(wgt, x, rS[rj]);
                        cs[u] += e;
                        cS2[u] = fmaf(wgt, x, cS2[u]);
                        int j = colbase + cloc[u];
                        int pidx = (j & 63) + ((is2j && labi[rj] < KCLS) ? 64 : 0);
                        g_pos[grow][pidx] = x;
                        g_pos[j][pidx2] = x;
                    } else {
                        rmx[rj] = fmaxf(rmx[rj], x);
                        cm[u] = fmaxf(cm[u], x);
                    }
                }
            }
            #pragma unroll
            for (int u = 0; u < 2; u++) {
                #pragma unroll
                for (int o = 4; o < 32; o <<= 1) {
                    cf[u]  += __shfl_xor_sync(0xffffffffu, cf[u],  o);
                    cs[u]  += __shfl_xor_sync(0xffffffffu, cs[u],  o);
                    cS2[u] += __shfl_xor_sync(0xffffffffu, cS2[u], o);
                    cm[u] = fmaxf(cm[u], __shfl_xor_sync(0xffffffffu, cm[u], o));
                }
                if (grp == 0) {
                    atomicAdd(&c_full[cloc[u]], cf[u]);
                    atomicAdd(&c_same[cloc[u]], cs[u]);
                    atomicAdd(&c_S[cloc[u]], cS2[u]);
                    atomicMax(&c_mx[cloc[u]], encf(cm[u]));
                }
            }
        }

        #pragma unroll
        for (int rj = 0; rj < 8; rj++) {
            int rloc = m0 + (rj >> 1) * 16 + grp + (rj & 1) * 8;
            float full = rfull[rj], sme = rsme[rj], Sa = rS[rj], mx = rmx[rj];
            #pragma unroll
            for (int o = 1; o < 4; o <<= 1) {
                full += __shfl_xor_sync(0xffffffffu, full, o);
                sme  += __shfl_xor_sync(0xffffffffu, sme,  o);
                Sa   += __shfl_xor_sync(0xffffffffu, Sa,   o);
                mx = fmaxf(mx, __shfl_xor_sync(0xffffffffu, mx, o));
            }
            if (t4 == 0) {
                atomicAdd(&s_full[rloc], full);
                atomicAdd(&s_same[rloc], sme);
                atomicAdd(&s_S[rloc], Sa);
                atomicMax(&s_mx[rloc], encf(mx));
            }
        }
    }

    __syncthreads();
    if (tid < 128) {
        g_part[rowbase + tid][bx] = make_float4(s_full[tid], s_same[tid], s_S[tid],
                                                __uint_as_float(s_mx[tid]));
        if (!diag)
            g_part[colbase + tid][by] = make_float4(c_full[tid], c_same[tid], c_S[tid],
                                                    __uint_as_float(c_mx[tid]));
    }
}

// ---------------- reduction kernel: one warp per row ----------------

__global__ void __launch_bounds__(256)
k_rows(const unsigned char* __restrict__ ovraw, float* out, int out_size) {
    __shared__ unsigned s_ovm;
    __shared__ float s_l[8];
    __shared__ int   s_c[8];
    __shared__ int   s_n[8];
    const int tid = threadIdx.x, lane = tid & 31, w = tid >> 5;
    if (tid == 0) s_ovm = sniff_ov(ovraw);
    __syncthreads();
    const unsigned ovm = s_ovm;
    const int row = blockIdx.x * 8 + w;

    float4 p = g_part[row][lane];
    float full = p.x, sme = p.y, S = p.z;
    unsigned mxe = __float_as_uint(p.w);
    #pragma unroll
    for (int o = 16; o > 0; o >>= 1) {
        full += __shfl_xor_sync(0xffffffffu, full, o);
        sme  += __shfl_xor_sync(0xffffffffu, sme,  o);
        S    += __shfl_xor_sync(0xffffffffu, S,    o);
        mxe = max(mxe, __shfl_xor_sync(0xffffffffu, mxe, o));
    }

    const int L = labelOf(row, ovm);
    const bool ovl = (L < KCLS) ? ((ovm >> L) & 1u) : false;
    const int cnt = ovl ? 128 : 64;
    const int selfidx = (row & 63) + ((row >= NH && L < KCLS) ? 64 : 0);
    const float mn = decf(mxe);

    int corr = 0;
    #pragma unroll
    for (int t2 = lane; t2 < 128; t2 += 32) {
        if (t2 < cnt) {
            float v = g_pos[row][t2];
            if (t2 != selfidx && v > mn) corr++;
        }
    }
    #pragma unroll
    for (int o = 16; o > 0; o >>= 1)
        corr += __shfl_xor_sync(0xffffffffu, corr, o);

    if (lane == 0) {
        float xself = g_pos[row][selfidx];
        float W = ovl ? 95.0f : 63.0f;
        s_l[w] = fmaf(W, logf(full - sme), -(S - xself));
        s_c[w] = corr;
        s_n[w] = cnt - 1;
    }
    __syncthreads();
    if (tid == 0) {
        float lt = 0.f; int ct = 0, nt = 0;
        #pragma unroll
        for (int i = 0; i < 8; i++) { lt += s_l[i]; ct += s_c[i]; nt += s_n[i]; }
        atomicAdd(&g_loss, lt);
        atomicAdd(&g_corr, ct);
        atomicAdd(&g_np, nt);
        __threadfence();
        unsigned d = atomicAdd(&g_done, 1u);
        if (d == gridDim.x - 1) {
            __threadfence();
            float npf = (float)g_np;
            if (out_size >= 1) out[0] = (float)g_corr / npf;
            if (out_size >= 2) out[1] = g_loss / npf;
        }
    }
}

extern "C" void kernel_launch(void* const* d_in, const int* in_sizes, int n_in,
                              void* d_out, int out_size) {
    const float* f1 = nullptr;
    const float* f2 = nullptr;
    const unsigned char* ov = nullptr;
    for (int i = 0; i < n_in; i++) {
        if (in_sizes[i] == NH * FD) {
            if (!f1) f1 = (const float*)d_in[i];
            else if (!f2) f2 = (const float*)d_in[i];
        } else if (in_sizes[i] == KCLS) {
            ov = (const unsigned char*)d_in[i];
        }
    }
    cudaFuncSetAttribute(k_main, cudaFuncAttributeMaxDynamicSharedMemorySize, SM_TOTAL);

    k_main<<<528, 256, SM_TOTAL>>>(f1, f2, ov);
    k_rows<<<512, 256>>>(ov, (float*)d_out, out_size);
}